// round 2
// baseline (speedup 1.0000x reference)
#include <cuda_runtime.h>
#include <math.h>

// ---------------- problem constants ----------------
#define NHEADS   8
#define NK       4
#define NSCALES  4
#define DMODEL   256
#define DKH      32           // DMODEL / NHEADS
#define NB       4
#define QH       64
#define QW       64
#define HWQ      (QH*QW)      // 4096
#define MQ       (NB*HWQ)     // 16384

// kf scale bases (floats): 4*wl*wl*256 each
// wl = 16,32,64,128 -> sizes 262144, 1048576, 4194304, 16777216
#define KF_TOTAL 22282240

// ---------------- scratch (device globals; no runtime alloc) ----------------
__device__ float g_q  [MQ * DMODEL];        // projected query
__device__ float g_off[MQ * DMODEL];        // offset logits (B,HW,256)
__device__ float g_A  [MQ * 128];           // attention weights after softmax
__device__ float g_kf [KF_TOTAL];           // projected keys, all scales
__device__ float g_F  [MQ * DMODEL];        // aggregated features (B,heads,HW,DK) flat

// ---------------- fp32 tiled GEMM: C = A[M,K] @ W[K,N] + bias[N] ----------------
// BM=64, BN=64, BK=16, 256 threads, 4x4 microtile. All dims divisible.
#define BM 64
#define BN 64
#define BK 16
__global__ void sgemm_bias(const float* __restrict__ A,
                           const float* __restrict__ W,
                           const float* __restrict__ bias,
                           float* __restrict__ C,
                           int M, int N, int Kdim)
{
    __shared__ float As[BK][BM];
    __shared__ float Bs[BK][BN];

    const int tid = threadIdx.x;           // 0..255
    const int tx  = tid & 15;              // col group
    const int ty  = tid >> 4;              // row group
    const int rowBase = blockIdx.y * BM;
    const int colBase = blockIdx.x * BN;

    // loaders
    const int ar = tid >> 2;               // 0..63 (row within A tile)
    const int ak = (tid & 3) * 4;          // k offset, float4
    const int wk = tid >> 4;               // 0..15 (k row within W tile)
    const int wc = (tid & 15) * 4;         // col offset, float4

    float acc[4][4] = {};

    for (int k0 = 0; k0 < Kdim; k0 += BK) {
        float4 av = *(const float4*)&A[(size_t)(rowBase + ar) * Kdim + k0 + ak];
        As[ak + 0][ar] = av.x;
        As[ak + 1][ar] = av.y;
        As[ak + 2][ar] = av.z;
        As[ak + 3][ar] = av.w;
        float4 wv = *(const float4*)&W[(size_t)(k0 + wk) * N + colBase + wc];
        *(float4*)&Bs[wk][wc] = wv;
        __syncthreads();

#pragma unroll
        for (int k = 0; k < BK; k++) {
            float4 a4 = *(float4*)&As[k][ty * 4];
            float4 b4 = *(float4*)&Bs[k][tx * 4];
            acc[0][0] += a4.x * b4.x; acc[0][1] += a4.x * b4.y;
            acc[0][2] += a4.x * b4.z; acc[0][3] += a4.x * b4.w;
            acc[1][0] += a4.y * b4.x; acc[1][1] += a4.y * b4.y;
            acc[1][2] += a4.y * b4.z; acc[1][3] += a4.y * b4.w;
            acc[2][0] += a4.z * b4.x; acc[2][1] += a4.z * b4.y;
            acc[2][2] += a4.z * b4.z; acc[2][3] += a4.z * b4.w;
            acc[3][0] += a4.w * b4.x; acc[3][1] += a4.w * b4.y;
            acc[3][2] += a4.w * b4.z; acc[3][3] += a4.w * b4.w;
        }
        __syncthreads();
    }

#pragma unroll
    for (int i = 0; i < 4; i++) {
        int row = rowBase + ty * 4 + i;
#pragma unroll
        for (int j = 0; j < 4; j++) {
            int col = colBase + tx * 4 + j;
            C[(size_t)row * N + col] = acc[i][j] + bias[col];
        }
    }
}

// ---------------- softmax over the 16 (scale,k) logits per (pixel, head) ----------------
__global__ void softmax16_kernel()
{
    int i = blockIdx.x * blockDim.x + threadIdx.x;
    if (i >= MQ * NHEADS) return;
    float* p = g_A + (size_t)(i >> 3) * 128 + (i & 7) * 16;
    float v[16];
    float m = -1e30f;
#pragma unroll
    for (int j = 0; j < 16; j++) { v[j] = p[j]; m = fmaxf(m, v[j]); }
    float sum = 0.f;
#pragma unroll
    for (int j = 0; j < 16; j++) { v[j] = __expf(v[j] - m); sum += v[j]; }
    float inv = 1.f / sum;
#pragma unroll
    for (int j = 0; j < 16; j++) p[j] = v[j] * inv;
}

// ---------------- bilinear sample + attention aggregation ----------------
// One warp per (b, head, pixel); lane = channel d (0..31).
__global__ void sample_agg_kernel(const float* __restrict__ ref_point)
{
    int gtid = blockIdx.x * blockDim.x + threadIdx.x;
    int warp = gtid >> 5;
    int lane = gtid & 31;
    if (warp >= NB * NHEADS * HWQ) return;

    int pix = warp & (HWQ - 1);
    int bh  = warp >> 12;            // b*8 + h
    int b   = bh >> 3;
    int h   = bh & 7;

    float rx = ref_point[pix * 2 + 0];
    float ry = ref_point[pix * 2 + 1];

    const float* offrow = g_off + (size_t)(b * HWQ + pix) * DMODEL + h * 32;
    const float* arow   = g_A   + (size_t)(b * HWQ + pix) * 128    + h * 16;

    float acc = 0.f;

    const int wls[4]   = {16, 32, 64, 128};
    const int bases[4] = {0, 262144, 1310720, 5505024};

#pragma unroll
    for (int s = 0; s < 4; s++) {
        const int wl = wls[s];
        const float* kfb = g_kf + bases[s] + (size_t)b * wl * wl * DMODEL + h * 32 + lane;
        const float fwl  = (float)wl;
        const float fwm1 = (float)(wl - 1);
        const float rxs = rx * fwm1;
        const float rys = ry * fwm1;

#pragma unroll
        for (int k = 0; k < 4; k++) {
            float ox = offrow[s * 8 + k * 2 + 0];
            float oy = offrow[s * 8 + k * 2 + 1];
            float px = rxs + ox;
            float py = rys + oy;
            // grid-normalize then grid_sample (align_corners=False) un-normalize
            float gx = 2.f * px / fwm1 - 1.f;
            float gy = 2.f * py / fwm1 - 1.f;
            float ix = ((gx + 1.f) * fwl - 1.f) * 0.5f;
            float iy = ((gy + 1.f) * fwl - 1.f) * 0.5f;

            float x0f = floorf(ix), y0f = floorf(iy);
            int x0 = (int)x0f, y0 = (int)y0f;
            float wx1 = ix - x0f, wy1 = iy - y0f;
            float wx0 = 1.f - wx1, wy0 = 1.f - wy1;

            bool inx0 = (x0 >= 0) & (x0 < wl);
            bool inx1 = (x0 + 1 >= 0) & (x0 + 1 < wl);
            bool iny0 = (y0 >= 0) & (y0 < wl);
            bool iny1 = (y0 + 1 >= 0) & (y0 + 1 < wl);

            float v = 0.f;
            if (inx0 & iny0) v += wx0 * wy0 * __ldg(&kfb[((size_t)y0 * wl + x0)       * DMODEL]);
            if (inx1 & iny0) v += wx1 * wy0 * __ldg(&kfb[((size_t)y0 * wl + x0 + 1)   * DMODEL]);
            if (inx0 & iny1) v += wx0 * wy1 * __ldg(&kfb[((size_t)(y0+1) * wl + x0)   * DMODEL]);
            if (inx1 & iny1) v += wx1 * wy1 * __ldg(&kfb[((size_t)(y0+1) * wl + x0+1) * DMODEL]);

            acc += arow[s * 4 + k] * v;
        }
    }

    // F layout: ((b*8+h)*HW + pix)*32 + d  == warp*32 + lane
    g_F[(size_t)warp * 32 + lane] = acc;
}

// ---------------- launch ----------------
extern "C" void kernel_launch(void* const* d_in, const int* in_sizes, int n_in,
                              void* d_out, int out_size)
{
    // Two possible input orderings:
    //  (a) reference-signature order: query, keys0..3, ref_point, Wq, bq, Wk, bk, Woff, boff, WA, bA, Wm, bm
    //  (b) setup_inputs dict order:   query, ref_point, Wq, bq, Wk, bk, Woff, boff, WA, bA, Wm, bm, keys0..3
    // Disambiguate by in_sizes[1]: keys0 has 262144 elements, ref_point has 8192.
    const float *query, *ref_point, *Wq, *bq, *Wk, *bk, *Woff, *boff, *WA, *bA, *Wm, *bm;
    const float* keys[4];

    if (in_sizes[1] == 262144) {
        // signature order
        query     = (const float*)d_in[0];
        keys[0]   = (const float*)d_in[1];
        keys[1]   = (const float*)d_in[2];
        keys[2]   = (const float*)d_in[3];
        keys[3]   = (const float*)d_in[4];
        ref_point = (const float*)d_in[5];
        Wq   = (const float*)d_in[6];
        bq   = (const float*)d_in[7];
        Wk   = (const float*)d_in[8];
        bk   = (const float*)d_in[9];
        Woff = (const float*)d_in[10];
        boff = (const float*)d_in[11];
        WA   = (const float*)d_in[12];
        bA   = (const float*)d_in[13];
        Wm   = (const float*)d_in[14];
        bm   = (const float*)d_in[15];
    } else {
        // setup_inputs dict order
        query     = (const float*)d_in[0];
        ref_point = (const float*)d_in[1];
        Wq   = (const float*)d_in[2];
        bq   = (const float*)d_in[3];
        Wk   = (const float*)d_in[4];
        bk   = (const float*)d_in[5];
        Woff = (const float*)d_in[6];
        boff = (const float*)d_in[7];
        WA   = (const float*)d_in[8];
        bA   = (const float*)d_in[9];
        Wm   = (const float*)d_in[10];
        bm   = (const float*)d_in[11];
        keys[0] = (const float*)d_in[12];
        keys[1] = (const float*)d_in[13];
        keys[2] = (const float*)d_in[14];
        keys[3] = (const float*)d_in[15];
    }
    float* out = (float*)d_out;

    float *q, *off, *A, *kf, *F;
    cudaGetSymbolAddress((void**)&q,   g_q);
    cudaGetSymbolAddress((void**)&off, g_off);
    cudaGetSymbolAddress((void**)&A,   g_A);
    cudaGetSymbolAddress((void**)&kf,  g_kf);
    cudaGetSymbolAddress((void**)&F,   g_F);

    // 1. q = query @ Wq + bq           (16384 x 256)
    sgemm_bias<<<dim3(DMODEL / BN, MQ / BM), 256>>>(query, Wq, bq, q, MQ, DMODEL, DMODEL);

    // 2. offset logits = q @ Woff + boff   (16384 x 256)
    sgemm_bias<<<dim3(DMODEL / BN, MQ / BM), 256>>>(q, Woff, boff, off, MQ, DMODEL, DMODEL);

    // 3. attention logits = q @ WA + bA    (16384 x 128), then softmax over 16/head
    sgemm_bias<<<dim3(128 / BN, MQ / BM), 256>>>(q, WA, bA, A, MQ, 128, DMODEL);
    softmax16_kernel<<<(MQ * NHEADS + 255) / 256, 256>>>();

    // 4. key projections per scale: kf_l = keys_l @ Wk + bk
    int base = 0;
    const int wls[4] = {16, 32, 64, 128};
    for (int s = 0; s < 4; s++) {
        int Ms = NB * wls[s] * wls[s];
        sgemm_bias<<<dim3(DMODEL / BN, Ms / BM), 256>>>(keys[s], Wk, bk, kf + base, Ms, DMODEL, DMODEL);
        base += Ms * DMODEL;
    }

    // 5. bilinear sampling + attention-weighted aggregation -> F
    {
        int nthreads = NB * NHEADS * HWQ * 32;   // one warp per (b,h,pixel)
        sample_agg_kernel<<<nthreads / 256, 256>>>(ref_point);
    }

    // 6. out = F @ Wm + bm   (16384 x 256)
    sgemm_bias<<<dim3(DMODEL / BN, MQ / BM), 256>>>(F, Wm, bm, out, MQ, DMODEL, DMODEL);
}

// round 4
// speedup vs baseline: 1.8088x; 1.8088x over previous
#include <cuda_runtime.h>
#include <math.h>
#include <stdint.h>

// ---------------- problem constants ----------------
#define NHEADS   8
#define NK       4
#define NSCALES  4
#define DMODEL   256
#define DKH      32           // DMODEL / NHEADS
#define NB       4
#define QH       64
#define QW       64
#define HWQ      (QH*QW)      // 4096
#define MQ       (NB*HWQ)     // 16384

// kf scale bases (floats): 4*wl*wl*256 each
#define KF_TOTAL 22282240

// ---------------- scratch (device globals; no runtime alloc) ----------------
__device__ float g_q  [MQ * DMODEL];
__device__ float g_off[MQ * DMODEL];
__device__ float g_A  [MQ * 128];
__device__ float g_kf [KF_TOTAL];
__device__ float g_F  [MQ * DMODEL];

// =====================================================================
// TF32 tensor-core GEMM: C = A[M,K] @ W[K,N] + bias[N]
// Block tile 128x128, BK=16, 256 threads (8 warps), warp tile 32x64.
// mma.sync.aligned.m16n8k8.row.col.f32.tf32.tf32.f32
// Requires: M%128==0, N%128==0, K%16==0.
// =====================================================================
#define GBM 128
#define GBN 128
#define GBK 16
#define SSTR 136   // smem row stride in words (128+8): conflict-free frag loads

__device__ __forceinline__ uint32_t f2tf32(float f) {
    uint32_t u;
    asm("cvt.rna.tf32.f32 %0, %1;" : "=r"(u) : "f"(f));
    return u;
}

__device__ __forceinline__ void mma_tf32(float* c, const uint32_t* a, uint32_t b0, uint32_t b1) {
    asm volatile(
        "mma.sync.aligned.m16n8k8.row.col.f32.tf32.tf32.f32 "
        "{%0,%1,%2,%3}, {%4,%5,%6,%7}, {%8,%9}, {%0,%1,%2,%3};"
        : "+f"(c[0]), "+f"(c[1]), "+f"(c[2]), "+f"(c[3])
        : "r"(a[0]), "r"(a[1]), "r"(a[2]), "r"(a[3]), "r"(b0), "r"(b1));
}

__global__ __launch_bounds__(256) void gemm_tf32_bias(
    const float* __restrict__ A,
    const float* __restrict__ W,
    const float* __restrict__ bias,
    float* __restrict__ C,
    int M, int N, int Kdim)
{
    // As[k][m] (transposed), Bs[k][n]
    __shared__ uint32_t As[GBK][SSTR];
    __shared__ uint32_t Bs[GBK][SSTR];

    const int tid  = threadIdx.x;
    const int lane = tid & 31;
    const int warp = tid >> 5;
    const int warpM = warp & 3;      // 4 warps over M: 32 rows each
    const int warpN = warp >> 2;     // 2 warps over N: 64 cols each
    const int g    = lane >> 2;      // groupID 0..7
    const int tig  = lane & 3;       // thread-in-group 0..3

    const int rowBase = blockIdx.y * GBM;
    const int colBase = blockIdx.x * GBN;

    // A loader: 512 float4 slots (128 m x 4 k4-groups); 2 per thread
    const int am0 = tid >> 2;            // 0..63
    const int am1 = am0 + 64;
    const int ak4 = (tid & 3) * 4;       // k offset
    // B loader: 512 float4 slots (16 k x 32 n4); 2 per thread
    const int bk0 = tid >> 5;            // 0..7
    const int bk1 = bk0 + 8;
    const int bn  = (tid & 31) * 4;

    float acc[2][8][4];
#pragma unroll
    for (int mi = 0; mi < 2; mi++)
#pragma unroll
        for (int ni = 0; ni < 8; ni++)
#pragma unroll
            for (int e = 0; e < 4; e++) acc[mi][ni][e] = 0.f;

    const int nIter = Kdim / GBK;

    // prefetch tile 0
    float4 pa0 = *(const float4*)&A[(size_t)(rowBase + am0) * Kdim + ak4];
    float4 pa1 = *(const float4*)&A[(size_t)(rowBase + am1) * Kdim + ak4];
    float4 pb0 = *(const float4*)&W[(size_t)bk0 * N + colBase + bn];
    float4 pb1 = *(const float4*)&W[(size_t)bk1 * N + colBase + bn];

    for (int it = 0; it < nIter; it++) {
        if (it) __syncthreads();

        // store staged tile to smem (convert to tf32)
        As[ak4 + 0][am0] = f2tf32(pa0.x);
        As[ak4 + 1][am0] = f2tf32(pa0.y);
        As[ak4 + 2][am0] = f2tf32(pa0.z);
        As[ak4 + 3][am0] = f2tf32(pa0.w);
        As[ak4 + 0][am1] = f2tf32(pa1.x);
        As[ak4 + 1][am1] = f2tf32(pa1.y);
        As[ak4 + 2][am1] = f2tf32(pa1.z);
        As[ak4 + 3][am1] = f2tf32(pa1.w);
        {
            uint4 v0 = make_uint4(f2tf32(pb0.x), f2tf32(pb0.y), f2tf32(pb0.z), f2tf32(pb0.w));
            uint4 v1 = make_uint4(f2tf32(pb1.x), f2tf32(pb1.y), f2tf32(pb1.z), f2tf32(pb1.w));
            *(uint4*)&Bs[bk0][bn] = v0;
            *(uint4*)&Bs[bk1][bn] = v1;
        }
        __syncthreads();

        // prefetch next tile
        if (it + 1 < nIter) {
            int k0 = (it + 1) * GBK;
            pa0 = *(const float4*)&A[(size_t)(rowBase + am0) * Kdim + k0 + ak4];
            pa1 = *(const float4*)&A[(size_t)(rowBase + am1) * Kdim + k0 + ak4];
            pb0 = *(const float4*)&W[(size_t)(k0 + bk0) * N + colBase + bn];
            pb1 = *(const float4*)&W[(size_t)(k0 + bk1) * N + colBase + bn];
        }

        // compute: two k-steps of 8
#pragma unroll
        for (int kk = 0; kk < GBK; kk += 8) {
            uint32_t af[2][4];
#pragma unroll
            for (int mi = 0; mi < 2; mi++) {
                int mrow = warpM * 32 + mi * 16;
                af[mi][0] = As[kk + tig    ][mrow + g];
                af[mi][1] = As[kk + tig    ][mrow + g + 8];
                af[mi][2] = As[kk + tig + 4][mrow + g];
                af[mi][3] = As[kk + tig + 4][mrow + g + 8];
            }
#pragma unroll
            for (int ni = 0; ni < 8; ni++) {
                int ncol = warpN * 64 + ni * 8;
                uint32_t b0 = Bs[kk + tig    ][ncol + g];
                uint32_t b1 = Bs[kk + tig + 4][ncol + g];
                mma_tf32(acc[0][ni], af[0], b0, b1);
                mma_tf32(acc[1][ni], af[1], b0, b1);
            }
        }
    }

    // epilogue: add bias, store (float2 per row-pair fragment)
#pragma unroll
    for (int mi = 0; mi < 2; mi++) {
        int r0 = rowBase + warpM * 32 + mi * 16 + g;
        int r1 = r0 + 8;
#pragma unroll
        for (int ni = 0; ni < 8; ni++) {
            int c0 = colBase + warpN * 64 + ni * 8 + tig * 2;
            float bz0 = __ldg(&bias[c0]);
            float bz1 = __ldg(&bias[c0 + 1]);
            float2 v0 = make_float2(acc[mi][ni][0] + bz0, acc[mi][ni][1] + bz1);
            float2 v1 = make_float2(acc[mi][ni][2] + bz0, acc[mi][ni][3] + bz1);
            *(float2*)&C[(size_t)r0 * N + c0] = v0;
            *(float2*)&C[(size_t)r1 * N + c0] = v1;
        }
    }
}

// ---------------- softmax over the 16 (scale,k) logits per (pixel, head) ----------------
__global__ void softmax16_kernel()
{
    int i = blockIdx.x * blockDim.x + threadIdx.x;
    if (i >= MQ * NHEADS) return;
    float* p = g_A + (size_t)(i >> 3) * 128 + (i & 7) * 16;
    float v[16];
    float m = -1e30f;
#pragma unroll
    for (int j = 0; j < 16; j++) { v[j] = p[j]; m = fmaxf(m, v[j]); }
    float sum = 0.f;
#pragma unroll
    for (int j = 0; j < 16; j++) { v[j] = __expf(v[j] - m); sum += v[j]; }
    float inv = 1.f / sum;
#pragma unroll
    for (int j = 0; j < 16; j++) p[j] = v[j] * inv;
}

// ---------------- bilinear sample + attention aggregation ----------------
// One warp per (b, head, pixel); lane = channel d (0..31).
__global__ void sample_agg_kernel(const float* __restrict__ ref_point)
{
    int gtid = blockIdx.x * blockDim.x + threadIdx.x;
    int warp = gtid >> 5;
    int lane = gtid & 31;
    if (warp >= NB * NHEADS * HWQ) return;

    int pix = warp & (HWQ - 1);
    int bh  = warp >> 12;            // b*8 + h
    int b   = bh >> 3;
    int h   = bh & 7;

    float rx = ref_point[pix * 2 + 0];
    float ry = ref_point[pix * 2 + 1];

    const float* offrow = g_off + (size_t)(b * HWQ + pix) * DMODEL + h * 32;
    const float* arow   = g_A   + (size_t)(b * HWQ + pix) * 128    + h * 16;

    float acc = 0.f;

    const int wls[4]   = {16, 32, 64, 128};
    const int bases[4] = {0, 262144, 1310720, 5505024};

#pragma unroll
    for (int s = 0; s < 4; s++) {
        const int wl = wls[s];
        const float* kfb = g_kf + bases[s] + (size_t)b * wl * wl * DMODEL + h * 32 + lane;
        const float fwl  = (float)wl;
        const float fwm1 = (float)(wl - 1);
        const float rxs = rx * fwm1;
        const float rys = ry * fwm1;

#pragma unroll
        for (int k = 0; k < 4; k++) {
            float ox = offrow[s * 8 + k * 2 + 0];
            float oy = offrow[s * 8 + k * 2 + 1];
            float px = rxs + ox;
            float py = rys + oy;
            float gx = 2.f * px / fwm1 - 1.f;
            float gy = 2.f * py / fwm1 - 1.f;
            float ix = ((gx + 1.f) * fwl - 1.f) * 0.5f;
            float iy = ((gy + 1.f) * fwl - 1.f) * 0.5f;

            float x0f = floorf(ix), y0f = floorf(iy);
            int x0 = (int)x0f, y0 = (int)y0f;
            float wx1 = ix - x0f, wy1 = iy - y0f;
            float wx0 = 1.f - wx1, wy0 = 1.f - wy1;

            bool inx0 = (x0 >= 0) & (x0 < wl);
            bool inx1 = (x0 + 1 >= 0) & (x0 + 1 < wl);
            bool iny0 = (y0 >= 0) & (y0 < wl);
            bool iny1 = (y0 + 1 >= 0) & (y0 + 1 < wl);

            float v = 0.f;
            if (inx0 & iny0) v += wx0 * wy0 * __ldg(&kfb[((size_t)y0 * wl + x0)       * DMODEL]);
            if (inx1 & iny0) v += wx1 * wy0 * __ldg(&kfb[((size_t)y0 * wl + x0 + 1)   * DMODEL]);
            if (inx0 & iny1) v += wx0 * wy1 * __ldg(&kfb[((size_t)(y0+1) * wl + x0)   * DMODEL]);
            if (inx1 & iny1) v += wx1 * wy1 * __ldg(&kfb[((size_t)(y0+1) * wl + x0+1) * DMODEL]);

            acc += arow[s * 4 + k] * v;
        }
    }

    g_F[(size_t)warp * 32 + lane] = acc;
}

// ---------------- launch ----------------
extern "C" void kernel_launch(void* const* d_in, const int* in_sizes, int n_in,
                              void* d_out, int out_size)
{
    const float *query, *ref_point, *Wq, *bq, *Wk, *bk, *Woff, *boff, *WA, *bA, *Wm, *bm;
    const float* keys[4];

    if (in_sizes[1] == 262144) {
        // reference-signature order
        query     = (const float*)d_in[0];
        keys[0]   = (const float*)d_in[1];
        keys[1]   = (const float*)d_in[2];
        keys[2]   = (const float*)d_in[3];
        keys[3]   = (const float*)d_in[4];
        ref_point = (const float*)d_in[5];
        Wq   = (const float*)d_in[6];
        bq   = (const float*)d_in[7];
        Wk   = (const float*)d_in[8];
        bk   = (const float*)d_in[9];
        Woff = (const float*)d_in[10];
        boff = (const float*)d_in[11];
        WA   = (const float*)d_in[12];
        bA   = (const float*)d_in[13];
        Wm   = (const float*)d_in[14];
        bm   = (const float*)d_in[15];
    } else {
        // setup_inputs dict order
        query     = (const float*)d_in[0];
        ref_point = (const float*)d_in[1];
        Wq   = (const float*)d_in[2];
        bq   = (const float*)d_in[3];
        Wk   = (const float*)d_in[4];
        bk   = (const float*)d_in[5];
        Woff = (const float*)d_in[6];
        boff = (const float*)d_in[7];
        WA   = (const float*)d_in[8];
        bA   = (const float*)d_in[9];
        Wm   = (const float*)d_in[10];
        bm   = (const float*)d_in[11];
        keys[0] = (const float*)d_in[12];
        keys[1] = (const float*)d_in[13];
        keys[2] = (const float*)d_in[14];
        keys[3] = (const float*)d_in[15];
    }
    float* out = (float*)d_out;

    float *q, *off, *A, *kf, *F;
    cudaGetSymbolAddress((void**)&q,   g_q);
    cudaGetSymbolAddress((void**)&off, g_off);
    cudaGetSymbolAddress((void**)&A,   g_A);
    cudaGetSymbolAddress((void**)&kf,  g_kf);
    cudaGetSymbolAddress((void**)&F,   g_F);

    // 1. q = query @ Wq + bq           (16384 x 256 x 256)
    gemm_tf32_bias<<<dim3(DMODEL / GBN, MQ / GBM), 256>>>(query, Wq, bq, q, MQ, DMODEL, DMODEL);

    // 2. offset logits = q @ Woff + boff
    gemm_tf32_bias<<<dim3(DMODEL / GBN, MQ / GBM), 256>>>(q, Woff, boff, off, MQ, DMODEL, DMODEL);

    // 3. attention logits = q @ WA + bA  (16384 x 128), then softmax per head
    gemm_tf32_bias<<<dim3(128 / GBN, MQ / GBM), 256>>>(q, WA, bA, A, MQ, 128, DMODEL);
    softmax16_kernel<<<(MQ * NHEADS + 255) / 256, 256>>>();

    // 4. key projections per scale
    int base = 0;
    const int wls[4] = {16, 32, 64, 128};
    for (int s = 0; s < 4; s++) {
        int Ms = NB * wls[s] * wls[s];
        gemm_tf32_bias<<<dim3(DMODEL / GBN, Ms / GBM), 256>>>(keys[s], Wk, bk, kf + base, Ms, DMODEL, DMODEL);
        base += Ms * DMODEL;
    }

    // 5. bilinear sampling + attention-weighted aggregation -> F
    {
        int nthreads = NB * NHEADS * HWQ * 32;
        sample_agg_kernel<<<nthreads / 256, 256>>>(ref_point);
    }

    // 6. out = F @ Wm + bm
    gemm_tf32_bias<<<dim3(DMODEL / GBN, MQ / GBM), 256>>>(F, Wm, bm, out, MQ, DMODEL, DMODEL);
}

// round 7
// speedup vs baseline: 1.8351x; 1.0145x over previous
#include <cuda_runtime.h>
#include <math.h>
#include <stdint.h>

// ---------------- problem constants ----------------
#define NHEADS   8
#define NK       4
#define NSCALES  4
#define DMODEL   256
#define DKH      32
#define NB       4
#define QH       64
#define QW       64
#define HWQ      (QH*QW)      // 4096
#define MQ       (NB*HWQ)     // 16384

#define KF_TOTAL 22282240

// ---------------- scratch ----------------
__device__ float g_q  [MQ * DMODEL];
__device__ float g_off[MQ * DMODEL];
__device__ float g_A  [MQ * 128];       // raw attention logits (softmax fused in sampler)
__device__ float g_kf [KF_TOTAL];
__device__ float g_F  [MQ * DMODEL];

// =====================================================================
// TF32 tensor-core GEMM, cp.async double-buffered.
// C = A[M,K] @ W[K,N] + bias[N].  Block 128x128, BK=16, 256 thr, warp 32x64.
// fp32 staged in smem; cvt.rna.tf32 applied on fragments (matches R4 numerics).
// =====================================================================
#define GBM 128
#define GBN 128
#define GBK 16
#define ASTR 20    // As row stride in words, [m][k] layout -> conflict-free frags
#define BSTR 136   // Bs row stride in words, [k][n] layout -> conflict-free frags

__device__ __forceinline__ void cp16(void* smem, const void* gmem) {
    uint32_t s = (uint32_t)__cvta_generic_to_shared(smem);
    asm volatile("cp.async.ca.shared.global [%0], [%1], 16;" :: "r"(s), "l"(gmem));
}

__device__ __forceinline__ uint32_t rna(uint32_t fbits) {
    uint32_t u;
    asm("cvt.rna.tf32.f32 %0, %1;" : "=r"(u) : "r"(fbits));
    return u;
}

__device__ __forceinline__ void mma_tf32(float* c, const uint32_t* a, uint32_t b0, uint32_t b1) {
    asm volatile(
        "mma.sync.aligned.m16n8k8.row.col.f32.tf32.tf32.f32 "
        "{%0,%1,%2,%3}, {%4,%5,%6,%7}, {%8,%9}, {%0,%1,%2,%3};"
        : "+f"(c[0]), "+f"(c[1]), "+f"(c[2]), "+f"(c[3])
        : "r"(a[0]), "r"(a[1]), "r"(a[2]), "r"(a[3]), "r"(b0), "r"(b1));
}

struct GemmSmem {
    uint32_t As[2][GBM][ASTR];   // 20480 B
    uint32_t Bs[2][GBK][BSTR];   // 17408 B
};

__device__ __forceinline__ void gemm_body(
    const float* __restrict__ A,
    const float* __restrict__ W,
    const float* __restrict__ bias,
    float* __restrict__ C,
    int N, int Kdim, int rowBase, int colBase,
    GemmSmem* sm)
{
    const int tid  = threadIdx.x;
    const int lane = tid & 31;
    const int warp = tid >> 5;
    const int warpM = warp & 3;
    const int warpN = warp >> 2;
    const int g    = lane >> 2;
    const int tig  = lane & 3;

    // A loader: 128m x 4 k4-groups, 2 float4/thread
    const int am0 = tid >> 2;
    const int am1 = am0 + 64;
    const int ak4 = (tid & 3) * 4;
    // B loader: 16k x 32 n4-groups, 2 float4/thread
    const int bk0 = tid >> 5;
    const int bk1 = bk0 + 8;
    const int bn  = (tid & 31) * 4;

    const float* Arow0 = &A[(size_t)(rowBase + am0) * Kdim + ak4];
    const float* Arow1 = &A[(size_t)(rowBase + am1) * Kdim + ak4];

    float acc[2][8][4];
#pragma unroll
    for (int mi = 0; mi < 2; mi++)
#pragma unroll
        for (int ni = 0; ni < 8; ni++)
#pragma unroll
            for (int e = 0; e < 4; e++) acc[mi][ni][e] = 0.f;

    const int nIter = Kdim / GBK;   // >= 2

#define LOAD_TILE(buf, k0)                                                     \
    do {                                                                       \
        cp16(&sm->As[buf][am0][ak4], Arow0 + (k0));                            \
        cp16(&sm->As[buf][am1][ak4], Arow1 + (k0));                            \
        cp16(&sm->Bs[buf][bk0][bn], &W[(size_t)((k0) + bk0) * N + colBase + bn]); \
        cp16(&sm->Bs[buf][bk1][bn], &W[(size_t)((k0) + bk1) * N + colBase + bn]); \
        asm volatile("cp.async.commit_group;" ::: "memory");                   \
    } while (0)

    LOAD_TILE(0, 0);
    LOAD_TILE(1, GBK);

    for (int it = 0; it < nIter; it++) {
        const int buf = it & 1;
        if (it + 1 < nIter)
            asm volatile("cp.async.wait_group 1;" ::: "memory");
        else
            asm volatile("cp.async.wait_group 0;" ::: "memory");
        __syncthreads();

#pragma unroll
        for (int kk = 0; kk < GBK; kk += 8) {
            uint32_t af[2][4];
#pragma unroll
            for (int mi = 0; mi < 2; mi++) {
                int mrow = warpM * 32 + mi * 16;
                af[mi][0] = rna(sm->As[buf][mrow + g    ][kk + tig    ]);
                af[mi][1] = rna(sm->As[buf][mrow + g + 8][kk + tig    ]);
                af[mi][2] = rna(sm->As[buf][mrow + g    ][kk + tig + 4]);
                af[mi][3] = rna(sm->As[buf][mrow + g + 8][kk + tig + 4]);
            }
#pragma unroll
            for (int ni = 0; ni < 8; ni++) {
                int ncol = warpN * 64 + ni * 8;
                uint32_t b0 = rna(sm->Bs[buf][kk + tig    ][ncol + g]);
                uint32_t b1 = rna(sm->Bs[buf][kk + tig + 4][ncol + g]);
                mma_tf32(acc[0][ni], af[0], b0, b1);
                mma_tf32(acc[1][ni], af[1], b0, b1);
            }
        }

        if (it + 2 < nIter) {
            __syncthreads();           // all warps done reading buf before overwrite
            LOAD_TILE(buf, (it + 2) * GBK);
        }
    }
#undef LOAD_TILE

    // epilogue
#pragma unroll
    for (int mi = 0; mi < 2; mi++) {
        int r0 = rowBase + warpM * 32 + mi * 16 + g;
        int r1 = r0 + 8;
#pragma unroll
        for (int ni = 0; ni < 8; ni++) {
            int c0 = colBase + warpN * 64 + ni * 8 + tig * 2;
            float bz0 = __ldg(&bias[c0]);
            float bz1 = __ldg(&bias[c0 + 1]);
            float2 v0 = make_float2(acc[mi][ni][0] + bz0, acc[mi][ni][1] + bz1);
            float2 v1 = make_float2(acc[mi][ni][2] + bz0, acc[mi][ni][3] + bz1);
            *(float2*)&C[(size_t)r0 * N + c0] = v0;
            *(float2*)&C[(size_t)r1 * N + c0] = v1;
        }
    }
}

__global__ __launch_bounds__(256) void gemm_tf32_bias(
    const float* __restrict__ A, const float* __restrict__ W,
    const float* __restrict__ bias, float* __restrict__ C,
    int N, int Kdim)
{
    __shared__ GemmSmem sm;
    gemm_body(A, W, bias, C, N, Kdim, blockIdx.y * GBM, blockIdx.x * GBN, &sm);
}

// fused dual-output GEMM: same A, two weight/bias/output sets
__global__ __launch_bounds__(256) void gemm_tf32_bias_dual(
    const float* __restrict__ A,
    const float* __restrict__ W1, const float* __restrict__ b1, float* __restrict__ C1, int N1,
    const float* __restrict__ W2, const float* __restrict__ b2, float* __restrict__ C2, int N2,
    int Kdim)
{
    __shared__ GemmSmem sm;
    const int nb1 = N1 / GBN;
    if ((int)blockIdx.x < nb1)
        gemm_body(A, W1, b1, C1, N1, Kdim, blockIdx.y * GBM, blockIdx.x * GBN, &sm);
    else
        gemm_body(A, W2, b2, C2, N2, Kdim, blockIdx.y * GBM, (blockIdx.x - nb1) * GBN, &sm);
}

// ---------------- bilinear sample + softmax + aggregation ----------------
// One warp per (b, head, pixel); lane = channel d (0..31). Softmax fused.
__global__ void sample_agg_kernel(const float* __restrict__ ref_point)
{
    int gtid = blockIdx.x * blockDim.x + threadIdx.x;
    int warp = gtid >> 5;
    int lane = gtid & 31;
    if (warp >= NB * NHEADS * HWQ) return;

    int pix = warp & (HWQ - 1);
    int bh  = warp >> 12;            // b*8 + h
    int b   = bh >> 3;
    int h   = bh & 7;

    float rx = ref_point[pix * 2 + 0];
    float ry = ref_point[pix * 2 + 1];

    const float* offrow = g_off + (size_t)(b * HWQ + pix) * DMODEL + h * 32;
    const float* lrow   = g_A   + (size_t)(b * HWQ + pix) * 128    + h * 16;

    // in-warp softmax over the 16 logits (broadcast loads, redundant per lane)
    float wgt[16];
    float m = -1e30f;
#pragma unroll
    for (int j = 0; j < 16; j++) { wgt[j] = __ldg(&lrow[j]); m = fmaxf(m, wgt[j]); }
    float sum = 0.f;
#pragma unroll
    for (int j = 0; j < 16; j++) { wgt[j] = __expf(wgt[j] - m); sum += wgt[j]; }
    float inv = 1.f / sum;

    float acc = 0.f;

    const int wls[4]   = {16, 32, 64, 128};
    const int bases[4] = {0, 262144, 1310720, 5505024};

#pragma unroll
    for (int s = 0; s < 4; s++) {
        const int wl = wls[s];
        const float* kfb = g_kf + bases[s] + (size_t)b * wl * wl * DMODEL + h * 32 + lane;
        const float fwl  = (float)wl;
        const float fwm1 = (float)(wl - 1);
        const float rxs = rx * fwm1;
        const float rys = ry * fwm1;

#pragma unroll
        for (int k = 0; k < 4; k++) {
            float ox = offrow[s * 8 + k * 2 + 0];
            float oy = offrow[s * 8 + k * 2 + 1];
            float px = rxs + ox;
            float py = rys + oy;
            float gx = 2.f * px / fwm1 - 1.f;
            float gy = 2.f * py / fwm1 - 1.f;
            float ix = ((gx + 1.f) * fwl - 1.f) * 0.5f;
            float iy = ((gy + 1.f) * fwl - 1.f) * 0.5f;

            float x0f = floorf(ix), y0f = floorf(iy);
            int x0 = (int)x0f, y0 = (int)y0f;
            float wx1 = ix - x0f, wy1 = iy - y0f;
            float wx0 = 1.f - wx1, wy0 = 1.f - wy1;

            bool inx0 = (x0 >= 0) & (x0 < wl);
            bool inx1 = (x0 + 1 >= 0) & (x0 + 1 < wl);
            bool iny0 = (y0 >= 0) & (y0 < wl);
            bool iny1 = (y0 + 1 >= 0) & (y0 + 1 < wl);

            float v = 0.f;
            if (inx0 & iny0) v += wx0 * wy0 * __ldg(&kfb[((size_t)y0 * wl + x0)       * DMODEL]);
            if (inx1 & iny0) v += wx1 * wy0 * __ldg(&kfb[((size_t)y0 * wl + x0 + 1)   * DMODEL]);
            if (inx0 & iny1) v += wx0 * wy1 * __ldg(&kfb[((size_t)(y0+1) * wl + x0)   * DMODEL]);
            if (inx1 & iny1) v += wx1 * wy1 * __ldg(&kfb[((size_t)(y0+1) * wl + x0+1) * DMODEL]);

            acc += (wgt[s * 4 + k] * inv) * v;
        }
    }

    g_F[(size_t)warp * 32 + lane] = acc;
}

// ---------------- launch ----------------
extern "C" void kernel_launch(void* const* d_in, const int* in_sizes, int n_in,
                              void* d_out, int out_size)
{
    const float *query, *ref_point, *Wq, *bq, *Wk, *bk, *Woff, *boff, *WA, *bA, *Wm, *bm;
    const float* keys[4];

    if (in_sizes[1] == 262144) {
        // reference-signature order
        query     = (const float*)d_in[0];
        keys[0]   = (const float*)d_in[1];
        keys[1]   = (const float*)d_in[2];
        keys[2]   = (const float*)d_in[3];
        keys[3]   = (const float*)d_in[4];
        ref_point = (const float*)d_in[5];
        Wq   = (const float*)d_in[6];
        bq   = (const float*)d_in[7];
        Wk   = (const float*)d_in[8];
        bk   = (const float*)d_in[9];
        Woff = (const float*)d_in[10];
        boff = (const float*)d_in[11];
        WA   = (const float*)d_in[12];
        bA   = (const float*)d_in[13];
        Wm   = (const float*)d_in[14];
        bm   = (const float*)d_in[15];
    } else {
        // setup_inputs dict order
        query     = (const float*)d_in[0];
        ref_point = (const float*)d_in[1];
        Wq   = (const float*)d_in[2];
        bq   = (const float*)d_in[3];
        Wk   = (const float*)d_in[4];
        bk   = (const float*)d_in[5];
        Woff = (const float*)d_in[6];
        boff = (const float*)d_in[7];
        WA   = (const float*)d_in[8];
        bA   = (const float*)d_in[9];
        Wm   = (const float*)d_in[10];
        bm   = (const float*)d_in[11];
        keys[0] = (const float*)d_in[12];
        keys[1] = (const float*)d_in[13];
        keys[2] = (const float*)d_in[14];
        keys[3] = (const float*)d_in[15];
    }
    float* out = (float*)d_out;

    float *q, *off, *A, *kf, *F;
    cudaGetSymbolAddress((void**)&q,   g_q);
    cudaGetSymbolAddress((void**)&off, g_off);
    cudaGetSymbolAddress((void**)&A,   g_A);
    cudaGetSymbolAddress((void**)&kf,  g_kf);
    cudaGetSymbolAddress((void**)&F,   g_F);

    // 1. q = query @ Wq + bq
    gemm_tf32_bias<<<dim3(DMODEL / GBN, MQ / GBM), 256>>>(query, Wq, bq, q, DMODEL, DMODEL);

    // 2+3 fused. off = q@Woff+boff (N=256), A-logits = q@WA+bA (N=128)
    gemm_tf32_bias_dual<<<dim3(DMODEL / GBN + 128 / GBN, MQ / GBM), 256>>>(
        q, Woff, boff, off, DMODEL, WA, bA, A, 128, DMODEL);

    // 4. key projections per scale
    int base = 0;
    const int wls[4] = {16, 32, 64, 128};
    for (int s = 0; s < 4; s++) {
        int Ms = NB * wls[s] * wls[s];
        gemm_tf32_bias<<<dim3(DMODEL / GBN, Ms / GBM), 256>>>(keys[s], Wk, bk, kf + base, DMODEL, DMODEL);
        base += Ms * DMODEL;
    }

    // 5. bilinear sampling + softmax + aggregation -> F
    {
        int nthreads = NB * NHEADS * HWQ * 32;
        sample_agg_kernel<<<nthreads / 256, 256>>>(ref_point);
    }

    // 6. out = F @ Wm + bm
    gemm_tf32_bias<<<dim3(DMODEL / GBN, MQ / GBM), 256>>>(F, Wm, bm, out, DMODEL, DMODEL);
}

// round 10
// speedup vs baseline: 1.9911x; 1.0850x over previous
#include <cuda_runtime.h>
#include <math.h>
#include <stdint.h>

// ---------------- problem constants ----------------
#define NHEADS   8
#define NK       4
#define NSCALES  4
#define DMODEL   256
#define DKH      32
#define NB       4
#define QH       64
#define QW       64
#define HWQ      (QH*QW)      // 4096
#define MQ       (NB*HWQ)     // 16384

#define KF_TOTAL 22282240

// ---------------- scratch ----------------
__device__ float g_q  [MQ * DMODEL];
__device__ float g_off[MQ * DMODEL];
__device__ float g_A  [MQ * 128];       // raw attention logits (softmax fused in sampler)
__device__ float g_kf [KF_TOTAL];
__device__ float g_F  [MQ * DMODEL];

// =====================================================================
// TF32 tensor-core GEMM, cp.async double-buffered.
// C = A[M,K] @ W[K,N] + bias[N].  Block 128x128, BK=16, 256 thr, warp 32x64.
// fp32 staged in smem; cvt.rna.tf32 applied on fragments.
// =====================================================================
#define GBM 128
#define GBN 128
#define GBK 16
#define ASTR 20    // As row stride in words, [m][k] layout -> conflict-free frags
#define BSTR 136   // Bs row stride in words, [k][n] layout -> conflict-free frags

__device__ __forceinline__ void cp16(void* smem, const void* gmem) {
    uint32_t s = (uint32_t)__cvta_generic_to_shared(smem);
    asm volatile("cp.async.ca.shared.global [%0], [%1], 16;" :: "r"(s), "l"(gmem));
}

__device__ __forceinline__ uint32_t rna(uint32_t fbits) {
    uint32_t u;
    asm("cvt.rna.tf32.f32 %0, %1;" : "=r"(u) : "r"(fbits));
    return u;
}

__device__ __forceinline__ void mma_tf32(float* c, const uint32_t* a, uint32_t b0, uint32_t b1) {
    asm volatile(
        "mma.sync.aligned.m16n8k8.row.col.f32.tf32.tf32.f32 "
        "{%0,%1,%2,%3}, {%4,%5,%6,%7}, {%8,%9}, {%0,%1,%2,%3};"
        : "+f"(c[0]), "+f"(c[1]), "+f"(c[2]), "+f"(c[3])
        : "r"(a[0]), "r"(a[1]), "r"(a[2]), "r"(a[3]), "r"(b0), "r"(b1));
}

struct GemmSmem {
    uint32_t As[2][GBM][ASTR];   // 20480 B
    uint32_t Bs[2][GBK][BSTR];   // 17408 B
};

__device__ __forceinline__ void gemm_body(
    const float* __restrict__ A,
    const float* __restrict__ W,
    const float* __restrict__ bias,
    float* __restrict__ C,
    int N, int Kdim, int rowBase, int colBase,
    GemmSmem* sm)
{
    const int tid  = threadIdx.x;
    const int lane = tid & 31;
    const int warp = tid >> 5;
    const int warpM = warp & 3;
    const int warpN = warp >> 2;
    const int g    = lane >> 2;
    const int tig  = lane & 3;

    const int am0 = tid >> 2;
    const int am1 = am0 + 64;
    const int ak4 = (tid & 3) * 4;
    const int bk0 = tid >> 5;
    const int bk1 = bk0 + 8;
    const int bn  = (tid & 31) * 4;

    const float* Arow0 = &A[(size_t)(rowBase + am0) * Kdim + ak4];
    const float* Arow1 = &A[(size_t)(rowBase + am1) * Kdim + ak4];

    float acc[2][8][4];
#pragma unroll
    for (int mi = 0; mi < 2; mi++)
#pragma unroll
        for (int ni = 0; ni < 8; ni++)
#pragma unroll
            for (int e = 0; e < 4; e++) acc[mi][ni][e] = 0.f;

    const int nIter = Kdim / GBK;   // >= 2

#define LOAD_TILE(buf, k0)                                                     \
    do {                                                                       \
        cp16(&sm->As[buf][am0][ak4], Arow0 + (k0));                            \
        cp16(&sm->As[buf][am1][ak4], Arow1 + (k0));                            \
        cp16(&sm->Bs[buf][bk0][bn], &W[(size_t)((k0) + bk0) * N + colBase + bn]); \
        cp16(&sm->Bs[buf][bk1][bn], &W[(size_t)((k0) + bk1) * N + colBase + bn]); \
        asm volatile("cp.async.commit_group;" ::: "memory");                   \
    } while (0)

    LOAD_TILE(0, 0);
    LOAD_TILE(1, GBK);

    for (int it = 0; it < nIter; it++) {
        const int buf = it & 1;
        if (it + 1 < nIter)
            asm volatile("cp.async.wait_group 1;" ::: "memory");
        else
            asm volatile("cp.async.wait_group 0;" ::: "memory");
        __syncthreads();

#pragma unroll
        for (int kk = 0; kk < GBK; kk += 8) {
            uint32_t af[2][4];
#pragma unroll
            for (int mi = 0; mi < 2; mi++) {
                int mrow = warpM * 32 + mi * 16;
                af[mi][0] = rna(sm->As[buf][mrow + g    ][kk + tig    ]);
                af[mi][1] = rna(sm->As[buf][mrow + g + 8][kk + tig    ]);
                af[mi][2] = rna(sm->As[buf][mrow + g    ][kk + tig + 4]);
                af[mi][3] = rna(sm->As[buf][mrow + g + 8][kk + tig + 4]);
            }
#pragma unroll
            for (int ni = 0; ni < 8; ni++) {
                int ncol = warpN * 64 + ni * 8;
                uint32_t b0 = rna(sm->Bs[buf][kk + tig    ][ncol + g]);
                uint32_t b1 = rna(sm->Bs[buf][kk + tig + 4][ncol + g]);
                mma_tf32(acc[0][ni], af[0], b0, b1);
                mma_tf32(acc[1][ni], af[1], b0, b1);
            }
        }

        if (it + 2 < nIter) {
            __syncthreads();
            LOAD_TILE(buf, (it + 2) * GBK);
        }
    }
#undef LOAD_TILE

    // epilogue
#pragma unroll
    for (int mi = 0; mi < 2; mi++) {
        int r0 = rowBase + warpM * 32 + mi * 16 + g;
        int r1 = r0 + 8;
#pragma unroll
        for (int ni = 0; ni < 8; ni++) {
            int c0 = colBase + warpN * 64 + ni * 8 + tig * 2;
            float bz0 = __ldg(&bias[c0]);
            float bz1 = __ldg(&bias[c0 + 1]);
            float2 v0 = make_float2(acc[mi][ni][0] + bz0, acc[mi][ni][1] + bz1);
            float2 v1 = make_float2(acc[mi][ni][2] + bz0, acc[mi][ni][3] + bz1);
            *(float2*)&C[(size_t)r0 * N + c0] = v0;
            *(float2*)&C[(size_t)r1 * N + c0] = v1;
        }
    }
}

__global__ __launch_bounds__(256) void gemm_tf32_bias(
    const float* __restrict__ A, const float* __restrict__ W,
    const float* __restrict__ bias, float* __restrict__ C,
    int N, int Kdim)
{
    __shared__ GemmSmem sm;
    gemm_body(A, W, bias, C, N, Kdim, blockIdx.y * GBM, blockIdx.x * GBN, &sm);
}

// fused dual-output GEMM: same A, two weight/bias/output sets
__global__ __launch_bounds__(256) void gemm_tf32_bias_dual(
    const float* __restrict__ A,
    const float* __restrict__ W1, const float* __restrict__ b1, float* __restrict__ C1, int N1,
    const float* __restrict__ W2, const float* __restrict__ b2, float* __restrict__ C2, int N2,
    int Kdim)
{
    __shared__ GemmSmem sm;
    const int nb1 = N1 / GBN;
    if ((int)blockIdx.x < nb1)
        gemm_body(A, W1, b1, C1, N1, Kdim, blockIdx.y * GBM, blockIdx.x * GBN, &sm);
    else
        gemm_body(A, W2, b2, C2, N2, Kdim, blockIdx.y * GBM, (blockIdx.x - nb1) * GBN, &sm);
}

// =====================================================================
// Segmented GEMM: q-projection + all 4 key projections in ONE launch.
// All segments: N=256, K=256, independent A/W/bias/C.
// y-blocks: [0,128) q | [128,136) k0 | [136,168) k1 | [168,296) k2 | [296,808) k3
// =====================================================================
__global__ __launch_bounds__(256) void gemm_tf32_seg(
    const float* __restrict__ query,
    const float* __restrict__ k0p, const float* __restrict__ k1p,
    const float* __restrict__ k2p, const float* __restrict__ k3p,
    const float* __restrict__ Wq, const float* __restrict__ bq,
    const float* __restrict__ Wk, const float* __restrict__ bk,
    float* __restrict__ qOut, float* __restrict__ kfOut)
{
    __shared__ GemmSmem sm;
    const int yb = blockIdx.y;

    const float* A;
    const float* W;
    const float* bias;
    float* C;
    int rowBase;

    if (yb < 128)      { A = query; W = Wq; bias = bq; C = qOut;            rowBase = yb * GBM; }
    else if (yb < 136) { A = k0p;   W = Wk; bias = bk; C = kfOut;           rowBase = (yb - 128) * GBM; }
    else if (yb < 168) { A = k1p;   W = Wk; bias = bk; C = kfOut + 262144;  rowBase = (yb - 136) * GBM; }
    else if (yb < 296) { A = k2p;   W = Wk; bias = bk; C = kfOut + 1310720; rowBase = (yb - 168) * GBM; }
    else               { A = k3p;   W = Wk; bias = bk; C = kfOut + 5505024; rowBase = (yb - 296) * GBM; }

    gemm_body(A, W, bias, C, DMODEL, DMODEL, rowBase, blockIdx.x * GBN, &sm);
}

// ---------------- bilinear sample + softmax + aggregation ----------------
// One warp per (b, head, pixel); lane = channel d (0..31). Softmax fused.
__global__ void sample_agg_kernel(const float* __restrict__ ref_point)
{
    int gtid = blockIdx.x * blockDim.x + threadIdx.x;
    int warp = gtid >> 5;
    int lane = gtid & 31;
    if (warp >= NB * NHEADS * HWQ) return;

    int pix = warp & (HWQ - 1);
    int bh  = warp >> 12;            // b*8 + h
    int b   = bh >> 3;
    int h   = bh & 7;

    float rx = ref_point[pix * 2 + 0];
    float ry = ref_point[pix * 2 + 1];

    const float* offrow = g_off + (size_t)(b * HWQ + pix) * DMODEL + h * 32;
    const float* lrow   = g_A   + (size_t)(b * HWQ + pix) * 128    + h * 16;

    // in-warp softmax over the 16 logits (broadcast loads, redundant per lane)
    float wgt[16];
    float m = -1e30f;
#pragma unroll
    for (int j = 0; j < 16; j++) { wgt[j] = __ldg(&lrow[j]); m = fmaxf(m, wgt[j]); }
    float sum = 0.f;
#pragma unroll
    for (int j = 0; j < 16; j++) { wgt[j] = __expf(wgt[j] - m); sum += wgt[j]; }
    float inv = 1.f / sum;

    float acc = 0.f;

    const int wls[4]   = {16, 32, 64, 128};
    const int bases[4] = {0, 262144, 1310720, 5505024};

#pragma unroll
    for (int s = 0; s < 4; s++) {
        const int wl = wls[s];
        const float* kfb = g_kf + bases[s] + (size_t)b * wl * wl * DMODEL + h * 32 + lane;
        const float fwl  = (float)wl;
        const float fwm1 = (float)(wl - 1);
        const float rxs = rx * fwm1;
        const float rys = ry * fwm1;

#pragma unroll
        for (int k = 0; k < 4; k++) {
            float ox = offrow[s * 8 + k * 2 + 0];
            float oy = offrow[s * 8 + k * 2 + 1];
            float px = rxs + ox;
            float py = rys + oy;
            float gx = 2.f * px / fwm1 - 1.f;
            float gy = 2.f * py / fwm1 - 1.f;
            float ix = ((gx + 1.f) * fwl - 1.f) * 0.5f;
            float iy = ((gy + 1.f) * fwl - 1.f) * 0.5f;

            float x0f = floorf(ix), y0f = floorf(iy);
            int x0 = (int)x0f, y0 = (int)y0f;
            float wx1 = ix - x0f, wy1 = iy - y0f;
            float wx0 = 1.f - wx1, wy0 = 1.f - wy1;

            bool inx0 = (x0 >= 0) & (x0 < wl);
            bool inx1 = (x0 + 1 >= 0) & (x0 + 1 < wl);
            bool iny0 = (y0 >= 0) & (y0 < wl);
            bool iny1 = (y0 + 1 >= 0) & (y0 + 1 < wl);

            float v = 0.f;
            if (inx0 & iny0) v += wx0 * wy0 * __ldg(&kfb[((size_t)y0 * wl + x0)       * DMODEL]);
            if (inx1 & iny0) v += wx1 * wy0 * __ldg(&kfb[((size_t)y0 * wl + x0 + 1)   * DMODEL]);
            if (inx0 & iny1) v += wx0 * wy1 * __ldg(&kfb[((size_t)(y0+1) * wl + x0)   * DMODEL]);
            if (inx1 & iny1) v += wx1 * wy1 * __ldg(&kfb[((size_t)(y0+1) * wl + x0+1) * DMODEL]);

            acc += (wgt[s * 4 + k] * inv) * v;
        }
    }

    g_F[(size_t)warp * 32 + lane] = acc;
}

// ---------------- launch ----------------
extern "C" void kernel_launch(void* const* d_in, const int* in_sizes, int n_in,
                              void* d_out, int out_size)
{
    const float *query, *ref_point, *Wq, *bq, *Wk, *bk, *Woff, *boff, *WA, *bA, *Wm, *bm;
    const float* keys[4];

    if (in_sizes[1] == 262144) {
        // reference-signature order
        query     = (const float*)d_in[0];
        keys[0]   = (const float*)d_in[1];
        keys[1]   = (const float*)d_in[2];
        keys[2]   = (const float*)d_in[3];
        keys[3]   = (const float*)d_in[4];
        ref_point = (const float*)d_in[5];
        Wq   = (const float*)d_in[6];
        bq   = (const float*)d_in[7];
        Wk   = (const float*)d_in[8];
        bk   = (const float*)d_in[9];
        Woff = (const float*)d_in[10];
        boff = (const float*)d_in[11];
        WA   = (const float*)d_in[12];
        bA   = (const float*)d_in[13];
        Wm   = (const float*)d_in[14];
        bm   = (const float*)d_in[15];
    } else {
        // setup_inputs dict order
        query     = (const float*)d_in[0];
        ref_point = (const float*)d_in[1];
        Wq   = (const float*)d_in[2];
        bq   = (const float*)d_in[3];
        Wk   = (const float*)d_in[4];
        bk   = (const float*)d_in[5];
        Woff = (const float*)d_in[6];
        boff = (const float*)d_in[7];
        WA   = (const float*)d_in[8];
        bA   = (const float*)d_in[9];
        Wm   = (const float*)d_in[10];
        bm   = (const float*)d_in[11];
        keys[0] = (const float*)d_in[12];
        keys[1] = (const float*)d_in[13];
        keys[2] = (const float*)d_in[14];
        keys[3] = (const float*)d_in[15];
    }
    float* out = (float*)d_out;

    float *q, *off, *A, *kf, *F;
    cudaGetSymbolAddress((void**)&q,   g_q);
    cudaGetSymbolAddress((void**)&off, g_off);
    cudaGetSymbolAddress((void**)&A,   g_A);
    cudaGetSymbolAddress((void**)&kf,  g_kf);
    cudaGetSymbolAddress((void**)&F,   g_F);

    // 1. segmented GEMM: q-proj + all key projections (one launch, 1616 blocks)
    gemm_tf32_seg<<<dim3(2, 808), 256>>>(
        query, keys[0], keys[1], keys[2], keys[3], Wq, bq, Wk, bk, q, kf);

    // 2. dual: off = q@Woff+boff (N=256), A-logits = q@WA+bA (N=128)
    gemm_tf32_bias_dual<<<dim3(DMODEL / GBN + 128 / GBN, MQ / GBM), 256>>>(
        q, Woff, boff, off, DMODEL, WA, bA, A, 128, DMODEL);

    // 3. bilinear sampling + softmax + aggregation -> F
    {
        int nthreads = NB * NHEADS * HWQ * 32;
        sample_agg_kernel<<<nthreads / 256, 256>>>(ref_point);
    }

    // 4. out = F @ Wm + bm
    gemm_tf32_bias<<<dim3(DMODEL / GBN, MQ / GBM), 256>>>(F, Wm, bm, out, DMODEL, DMODEL);
}

// round 11
// speedup vs baseline: 2.1510x; 1.0803x over previous
#include <cuda_runtime.h>
#include <math.h>
#include <stdint.h>

// ---------------- problem constants ----------------
#define NHEADS   8
#define NK       4
#define NSCALES  4
#define DMODEL   256
#define DKH      32
#define NB       4
#define QH       64
#define QW       64
#define HWQ      (QH*QW)      // 4096
#define MQ       (NB*HWQ)     // 16384

#define KF_TOTAL 22282240

// ---------------- scratch ----------------
__device__ float g_q  [MQ * DMODEL];
__device__ float g_off[MQ * DMODEL];
__device__ float g_A  [MQ * 128];       // raw attention logits (softmax fused in sampler)
__device__ float g_kf [KF_TOTAL];
__device__ float g_F  [MQ * DMODEL];

// =====================================================================
// TF32 tensor-core GEMM, 4-stage cp.async pipeline, ONE barrier/iter.
// C = A[M,K] @ W[K,N] + bias[N].  Block 128x128, BK=16, 256 thr, warp 32x64.
// fp32 staged in smem; cvt.rna.tf32 applied on fragments.
// =====================================================================
#define GBM 128
#define GBN 128
#define GBK 16
#define NSTAGE 4
#define ASTR 20    // As row stride in words, [m][k] layout -> conflict-free frags
#define BSTR 136   // Bs row stride in words, [k][n] layout -> conflict-free frags

struct GemmSmem4 {
    uint32_t As[NSTAGE][GBM][ASTR];   // 4 * 10240 B
    uint32_t Bs[NSTAGE][GBK][BSTR];   // 4 *  8704 B
};
#define GEMM_SMEM_BYTES (sizeof(GemmSmem4))   // 75776

__device__ __forceinline__ void cp16(void* smem, const void* gmem) {
    uint32_t s = (uint32_t)__cvta_generic_to_shared(smem);
    asm volatile("cp.async.ca.shared.global [%0], [%1], 16;" :: "r"(s), "l"(gmem));
}

__device__ __forceinline__ uint32_t rna(uint32_t fbits) {
    uint32_t u;
    asm("cvt.rna.tf32.f32 %0, %1;" : "=r"(u) : "r"(fbits));
    return u;
}

__device__ __forceinline__ void mma_tf32(float* c, const uint32_t* a, uint32_t b0, uint32_t b1) {
    asm volatile(
        "mma.sync.aligned.m16n8k8.row.col.f32.tf32.tf32.f32 "
        "{%0,%1,%2,%3}, {%4,%5,%6,%7}, {%8,%9}, {%0,%1,%2,%3};"
        : "+f"(c[0]), "+f"(c[1]), "+f"(c[2]), "+f"(c[3])
        : "r"(a[0]), "r"(a[1]), "r"(a[2]), "r"(a[3]), "r"(b0), "r"(b1));
}

__device__ __forceinline__ void gemm_body(
    const float* __restrict__ A,
    const float* __restrict__ W,
    const float* __restrict__ bias,
    float* __restrict__ C,
    int N, int Kdim, int rowBase, int colBase,
    GemmSmem4* sm)
{
    const int tid  = threadIdx.x;
    const int lane = tid & 31;
    const int warp = tid >> 5;
    const int warpM = warp & 3;
    const int warpN = warp >> 2;
    const int g    = lane >> 2;
    const int tig  = lane & 3;

    const int am0 = tid >> 2;
    const int am1 = am0 + 64;
    const int ak4 = (tid & 3) * 4;
    const int bk0 = tid >> 5;
    const int bk1 = bk0 + 8;
    const int bn  = (tid & 31) * 4;

    const float* Arow0 = &A[(size_t)(rowBase + am0) * Kdim + ak4];
    const float* Arow1 = &A[(size_t)(rowBase + am1) * Kdim + ak4];

    float acc[2][8][4];
#pragma unroll
    for (int mi = 0; mi < 2; mi++)
#pragma unroll
        for (int ni = 0; ni < 8; ni++)
#pragma unroll
            for (int e = 0; e < 4; e++) acc[mi][ni][e] = 0.f;

    const int nIter = Kdim / GBK;   // 16 for all our calls (>= NSTAGE-1 required)

#define LOAD_TILE(buf, k0)                                                     \
    do {                                                                       \
        cp16(&sm->As[buf][am0][ak4], Arow0 + (k0));                            \
        cp16(&sm->As[buf][am1][ak4], Arow1 + (k0));                            \
        cp16(&sm->Bs[buf][bk0][bn], &W[(size_t)((k0) + bk0) * N + colBase + bn]); \
        cp16(&sm->Bs[buf][bk1][bn], &W[(size_t)((k0) + bk1) * N + colBase + bn]); \
        asm volatile("cp.async.commit_group;" ::: "memory");                   \
    } while (0)

    // prologue: 3 tiles in flight
    LOAD_TILE(0, 0);
    LOAD_TILE(1, GBK);
    LOAD_TILE(2, 2 * GBK);

    for (int it = 0; it < nIter; it++) {
        const int buf = it & 3;
        if (it + 2 < nIter)
            asm volatile("cp.async.wait_group 2;" ::: "memory");
        else if (it + 1 < nIter)
            asm volatile("cp.async.wait_group 1;" ::: "memory");
        else
            asm volatile("cp.async.wait_group 0;" ::: "memory");
        __syncthreads();   // single barrier per iteration

#pragma unroll
        for (int kk = 0; kk < GBK; kk += 8) {
            uint32_t af[2][4];
#pragma unroll
            for (int mi = 0; mi < 2; mi++) {
                int mrow = warpM * 32 + mi * 16;
                af[mi][0] = rna(sm->As[buf][mrow + g    ][kk + tig    ]);
                af[mi][1] = rna(sm->As[buf][mrow + g + 8][kk + tig    ]);
                af[mi][2] = rna(sm->As[buf][mrow + g    ][kk + tig + 4]);
                af[mi][3] = rna(sm->As[buf][mrow + g + 8][kk + tig + 4]);
            }
#pragma unroll
            for (int ni = 0; ni < 8; ni++) {
                int ncol = warpN * 64 + ni * 8;
                uint32_t b0 = rna(sm->Bs[buf][kk + tig    ][ncol + g]);
                uint32_t b1 = rna(sm->Bs[buf][kk + tig + 4][ncol + g]);
                mma_tf32(acc[0][ni], af[0], b0, b1);
                mma_tf32(acc[1][ni], af[1], b0, b1);
            }
        }

        // load tile it+3 into buffer (it+3)&3: held tile it-1, which every
        // warp finished before passing THIS iteration's barrier -> safe.
        if (it + 3 < nIter)
            LOAD_TILE((it + 3) & 3, (it + 3) * GBK);
    }
#undef LOAD_TILE

    // epilogue
#pragma unroll
    for (int mi = 0; mi < 2; mi++) {
        int r0 = rowBase + warpM * 32 + mi * 16 + g;
        int r1 = r0 + 8;
#pragma unroll
        for (int ni = 0; ni < 8; ni++) {
            int c0 = colBase + warpN * 64 + ni * 8 + tig * 2;
            float bz0 = __ldg(&bias[c0]);
            float bz1 = __ldg(&bias[c0 + 1]);
            float2 v0 = make_float2(acc[mi][ni][0] + bz0, acc[mi][ni][1] + bz1);
            float2 v1 = make_float2(acc[mi][ni][2] + bz0, acc[mi][ni][3] + bz1);
            *(float2*)&C[(size_t)r0 * N + c0] = v0;
            *(float2*)&C[(size_t)r1 * N + c0] = v1;
        }
    }
}

__global__ __launch_bounds__(256) void gemm_tf32_bias(
    const float* __restrict__ A, const float* __restrict__ W,
    const float* __restrict__ bias, float* __restrict__ C,
    int N, int Kdim)
{
    extern __shared__ uint8_t smem_raw[];
    gemm_body(A, W, bias, C, N, Kdim, blockIdx.y * GBM, blockIdx.x * GBN,
              reinterpret_cast<GemmSmem4*>(smem_raw));
}

// fused dual-output GEMM: same A, two weight/bias/output sets
__global__ __launch_bounds__(256) void gemm_tf32_bias_dual(
    const float* __restrict__ A,
    const float* __restrict__ W1, const float* __restrict__ b1, float* __restrict__ C1, int N1,
    const float* __restrict__ W2, const float* __restrict__ b2, float* __restrict__ C2, int N2,
    int Kdim)
{
    extern __shared__ uint8_t smem_raw[];
    GemmSmem4* sm = reinterpret_cast<GemmSmem4*>(smem_raw);
    const int nb1 = N1 / GBN;
    if ((int)blockIdx.x < nb1)
        gemm_body(A, W1, b1, C1, N1, Kdim, blockIdx.y * GBM, blockIdx.x * GBN, sm);
    else
        gemm_body(A, W2, b2, C2, N2, Kdim, blockIdx.y * GBM, (blockIdx.x - nb1) * GBN, sm);
}

// =====================================================================
// Segmented GEMM: q-projection + all 4 key projections in ONE launch.
// y-blocks: [0,128) q | [128,136) k0 | [136,168) k1 | [168,296) k2 | [296,808) k3
// =====================================================================
__global__ __launch_bounds__(256) void gemm_tf32_seg(
    const float* __restrict__ query,
    const float* __restrict__ k0p, const float* __restrict__ k1p,
    const float* __restrict__ k2p, const float* __restrict__ k3p,
    const float* __restrict__ Wq, const float* __restrict__ bq,
    const float* __restrict__ Wk, const float* __restrict__ bk,
    float* __restrict__ qOut, float* __restrict__ kfOut)
{
    extern __shared__ uint8_t smem_raw[];
    GemmSmem4* sm = reinterpret_cast<GemmSmem4*>(smem_raw);
    const int yb = blockIdx.y;

    const float* A;
    const float* W;
    const float* bias;
    float* C;
    int rowBase;

    if (yb < 128)      { A = query; W = Wq; bias = bq; C = qOut;            rowBase = yb * GBM; }
    else if (yb < 136) { A = k0p;   W = Wk; bias = bk; C = kfOut;           rowBase = (yb - 128) * GBM; }
    else if (yb < 168) { A = k1p;   W = Wk; bias = bk; C = kfOut + 262144;  rowBase = (yb - 136) * GBM; }
    else if (yb < 296) { A = k2p;   W = Wk; bias = bk; C = kfOut + 1310720; rowBase = (yb - 168) * GBM; }
    else               { A = k3p;   W = Wk; bias = bk; C = kfOut + 5505024; rowBase = (yb - 296) * GBM; }

    gemm_body(A, W, bias, C, DMODEL, DMODEL, rowBase, blockIdx.x * GBN, sm);
}

// ---------------- bilinear sample + softmax + aggregation ----------------
// One warp per (b, head, pixel); lane = channel d (0..31).
// Softmax + offset loads done via 2 coalesced lane loads + warp shuffles
// (keeps the LSU free for the gather taps, which bound this kernel).
__global__ void sample_agg_kernel(const float* __restrict__ ref_point)
{
    int gtid = blockIdx.x * blockDim.x + threadIdx.x;
    int warp = gtid >> 5;
    int lane = gtid & 31;
    if (warp >= NB * NHEADS * HWQ) return;

    int pix = warp & (HWQ - 1);
    int bh  = warp >> 12;            // b*8 + h
    int b   = bh >> 3;
    int h   = bh & 7;

    float rx = ref_point[pix * 2 + 0];
    float ry = ref_point[pix * 2 + 1];

    const float* offrow = g_off + (size_t)(b * HWQ + pix) * DMODEL + h * 32;
    const float* lrow   = g_A   + (size_t)(b * HWQ + pix) * 128    + h * 16;

    // coalesced: lane j loads offset element j (32 floats) and logit j (<16)
    float off_reg = __ldg(&offrow[lane]);
    float lv = (lane < 16) ? __ldg(&lrow[lane]) : -1e30f;

    // warp softmax over 16 logits via butterfly (lanes >=16 contribute -inf/0)
    float mx = lv;
#pragma unroll
    for (int d = 16; d; d >>= 1) mx = fmaxf(mx, __shfl_xor_sync(0xFFFFFFFFu, mx, d));
    float e = __expf(lv - mx);
    float ssum = e;
#pragma unroll
    for (int d = 16; d; d >>= 1) ssum += __shfl_xor_sync(0xFFFFFFFFu, ssum, d);
    float wnorm = e / ssum;          // valid on lanes 0..15

    float acc = 0.f;

    const int wls[4]   = {16, 32, 64, 128};
    const int bases[4] = {0, 262144, 1310720, 5505024};

#pragma unroll
    for (int s = 0; s < 4; s++) {
        const int wl = wls[s];
        const float* kfb = g_kf + bases[s] + (size_t)b * wl * wl * DMODEL + h * 32 + lane;
        const float fwl  = (float)wl;
        const float fwm1 = (float)(wl - 1);
        const float rxs = rx * fwm1;
        const float rys = ry * fwm1;

#pragma unroll
        for (int k = 0; k < 4; k++) {
            float ox = __shfl_sync(0xFFFFFFFFu, off_reg, s * 8 + k * 2);
            float oy = __shfl_sync(0xFFFFFFFFu, off_reg, s * 8 + k * 2 + 1);
            float wgt = __shfl_sync(0xFFFFFFFFu, wnorm, s * 4 + k);

            float px = rxs + ox;
            float py = rys + oy;
            float gx = 2.f * px / fwm1 - 1.f;
            float gy = 2.f * py / fwm1 - 1.f;
            float ix = ((gx + 1.f) * fwl - 1.f) * 0.5f;
            float iy = ((gy + 1.f) * fwl - 1.f) * 0.5f;

            float x0f = floorf(ix), y0f = floorf(iy);
            int x0 = (int)x0f, y0 = (int)y0f;
            float wx1 = ix - x0f, wy1 = iy - y0f;
            float wx0 = 1.f - wx1, wy0 = 1.f - wy1;

            bool inx0 = (x0 >= 0) & (x0 < wl);
            bool inx1 = (x0 + 1 >= 0) & (x0 + 1 < wl);
            bool iny0 = (y0 >= 0) & (y0 < wl);
            bool iny1 = (y0 + 1 >= 0) & (y0 + 1 < wl);

            float v = 0.f;
            if (inx0 & iny0) v += wx0 * wy0 * __ldg(&kfb[((size_t)y0 * wl + x0)       * DMODEL]);
            if (inx1 & iny0) v += wx1 * wy0 * __ldg(&kfb[((size_t)y0 * wl + x0 + 1)   * DMODEL]);
            if (inx0 & iny1) v += wx0 * wy1 * __ldg(&kfb[((size_t)(y0+1) * wl + x0)   * DMODEL]);
            if (inx1 & iny1) v += wx1 * wy1 * __ldg(&kfb[((size_t)(y0+1) * wl + x0+1) * DMODEL]);

            acc += wgt * v;
        }
    }

    g_F[(size_t)warp * 32 + lane] = acc;
}

// ---------------- launch ----------------
extern "C" void kernel_launch(void* const* d_in, const int* in_sizes, int n_in,
                              void* d_out, int out_size)
{
    const float *query, *ref_point, *Wq, *bq, *Wk, *bk, *Woff, *boff, *WA, *bA, *Wm, *bm;
    const float* keys[4];

    if (in_sizes[1] == 262144) {
        // reference-signature order
        query     = (const float*)d_in[0];
        keys[0]   = (const float*)d_in[1];
        keys[1]   = (const float*)d_in[2];
        keys[2]   = (const float*)d_in[3];
        keys[3]   = (const float*)d_in[4];
        ref_point = (const float*)d_in[5];
        Wq   = (const float*)d_in[6];
        bq   = (const float*)d_in[7];
        Wk   = (const float*)d_in[8];
        bk   = (const float*)d_in[9];
        Woff = (const float*)d_in[10];
        boff = (const float*)d_in[11];
        WA   = (const float*)d_in[12];
        bA   = (const float*)d_in[13];
        Wm   = (const float*)d_in[14];
        bm   = (const float*)d_in[15];
    } else {
        // setup_inputs dict order
        query     = (const float*)d_in[0];
        ref_point = (const float*)d_in[1];
        Wq   = (const float*)d_in[2];
        bq   = (const float*)d_in[3];
        Wk   = (const float*)d_in[4];
        bk   = (const float*)d_in[5];
        Woff = (const float*)d_in[6];
        boff = (const float*)d_in[7];
        WA   = (const float*)d_in[8];
        bA   = (const float*)d_in[9];
        Wm   = (const float*)d_in[10];
        bm   = (const float*)d_in[11];
        keys[0] = (const float*)d_in[12];
        keys[1] = (const float*)d_in[13];
        keys[2] = (const float*)d_in[14];
        keys[3] = (const float*)d_in[15];
    }
    float* out = (float*)d_out;

    float *q, *off, *A, *kf, *F;
    cudaGetSymbolAddress((void**)&q,   g_q);
    cudaGetSymbolAddress((void**)&off, g_off);
    cudaGetSymbolAddress((void**)&A,   g_A);
    cudaGetSymbolAddress((void**)&kf,  g_kf);
    cudaGetSymbolAddress((void**)&F,   g_F);

    // opt-in to >48KB dynamic smem (executes immediately; not captured)
    cudaFuncSetAttribute(gemm_tf32_seg,
                         cudaFuncAttributeMaxDynamicSharedMemorySize, (int)GEMM_SMEM_BYTES);
    cudaFuncSetAttribute(gemm_tf32_bias_dual,
                         cudaFuncAttributeMaxDynamicSharedMemorySize, (int)GEMM_SMEM_BYTES);
    cudaFuncSetAttribute(gemm_tf32_bias,
                         cudaFuncAttributeMaxDynamicSharedMemorySize, (int)GEMM_SMEM_BYTES);

    // 1. segmented GEMM: q-proj + all key projections (one launch, 1616 blocks)
    gemm_tf32_seg<<<dim3(2, 808), 256, GEMM_SMEM_BYTES>>>(
        query, keys[0], keys[1], keys[2], keys[3], Wq, bq, Wk, bk, q, kf);

    // 2. dual: off = q@Woff+boff (N=256), A-logits = q@WA+bA (N=128)
    gemm_tf32_bias_dual<<<dim3(DMODEL / GBN + 128 / GBN, MQ / GBM), 256, GEMM_SMEM_BYTES>>>(
        q, Woff, boff, off, DMODEL, WA, bA, A, 128, DMODEL);

    // 3. bilinear sampling + softmax + aggregation -> F
    {
        int nthreads = NB * NHEADS * HWQ * 32;
        sample_agg_kernel<<<nthreads / 256, 256>>>(ref_point);
    }

    // 4. out = F @ Wm + bm
    gemm_tf32_bias<<<dim3(DMODEL / GBN, MQ / GBM), 256, GEMM_SMEM_BYTES>>>(F, Wm, bm, out, DMODEL, DMODEL);
}

// round 12
// speedup vs baseline: 2.1567x; 1.0026x over previous
#include <cuda_runtime.h>
#include <math.h>
#include <stdint.h>

// ---------------- problem constants ----------------
#define NHEADS   8
#define NK       4
#define NSCALES  4
#define DMODEL   256
#define DKH      32
#define NB       4
#define QH       64
#define QW       64
#define HWQ      (QH*QW)      // 4096
#define MQ       (NB*HWQ)     // 16384

#define KF_TOTAL 22282240

// ---------------- scratch ----------------
__device__ float g_q  [MQ * DMODEL];
__device__ float g_off[MQ * DMODEL];
__device__ float g_A  [MQ * 128];       // raw attention logits (softmax fused in sampler)
__device__ float g_kf [KF_TOTAL];
__device__ float g_F  [MQ * DMODEL];

// =====================================================================
// TF32 tensor-core GEMM, 4-stage cp.async pipeline, ONE barrier/iter.
// Fragment loads batched per k-step to overlap LDS latencies.
// C = A[M,K] @ W[K,N] + bias[N].  Block 128x128, BK=16, 256 thr, warp 32x64.
// =====================================================================
#define GBM 128
#define GBN 128
#define GBK 16
#define NSTAGE 4
#define ASTR 20    // As row stride in words, [m][k] layout -> conflict-free frags
#define BSTR 136   // Bs row stride in words, [k][n] layout -> conflict-free frags

struct GemmSmem4 {
    uint32_t As[NSTAGE][GBM][ASTR];   // 4 * 10240 B
    uint32_t Bs[NSTAGE][GBK][BSTR];   // 4 *  8704 B
};
#define GEMM_SMEM_BYTES (sizeof(GemmSmem4))   // 75776

__device__ __forceinline__ void cp16(void* smem, const void* gmem) {
    uint32_t s = (uint32_t)__cvta_generic_to_shared(smem);
    asm volatile("cp.async.ca.shared.global [%0], [%1], 16;" :: "r"(s), "l"(gmem));
}

__device__ __forceinline__ uint32_t rna(uint32_t fbits) {
    uint32_t u;
    asm("cvt.rna.tf32.f32 %0, %1;" : "=r"(u) : "r"(fbits));
    return u;
}

__device__ __forceinline__ void mma_tf32(float* c, const uint32_t* a, uint32_t b0, uint32_t b1) {
    asm volatile(
        "mma.sync.aligned.m16n8k8.row.col.f32.tf32.tf32.f32 "
        "{%0,%1,%2,%3}, {%4,%5,%6,%7}, {%8,%9}, {%0,%1,%2,%3};"
        : "+f"(c[0]), "+f"(c[1]), "+f"(c[2]), "+f"(c[3])
        : "r"(a[0]), "r"(a[1]), "r"(a[2]), "r"(a[3]), "r"(b0), "r"(b1));
}

__device__ __forceinline__ void gemm_body(
    const float* __restrict__ A,
    const float* __restrict__ W,
    const float* __restrict__ bias,
    float* __restrict__ C,
    int N, int Kdim, int rowBase, int colBase,
    GemmSmem4* sm)
{
    const int tid  = threadIdx.x;
    const int lane = tid & 31;
    const int warp = tid >> 5;
    const int warpM = warp & 3;
    const int warpN = warp >> 2;
    const int g    = lane >> 2;
    const int tig  = lane & 3;

    const int am0 = tid >> 2;
    const int am1 = am0 + 64;
    const int ak4 = (tid & 3) * 4;
    const int bk0 = tid >> 5;
    const int bk1 = bk0 + 8;
    const int bn  = (tid & 31) * 4;

    const float* Arow0 = &A[(size_t)(rowBase + am0) * Kdim + ak4];
    const float* Arow1 = &A[(size_t)(rowBase + am1) * Kdim + ak4];

    float acc[2][8][4];
#pragma unroll
    for (int mi = 0; mi < 2; mi++)
#pragma unroll
        for (int ni = 0; ni < 8; ni++)
#pragma unroll
            for (int e = 0; e < 4; e++) acc[mi][ni][e] = 0.f;

    const int nIter = Kdim / GBK;   // 16 for all our calls

#define LOAD_TILE(buf, k0)                                                     \
    do {                                                                       \
        cp16(&sm->As[buf][am0][ak4], Arow0 + (k0));                            \
        cp16(&sm->As[buf][am1][ak4], Arow1 + (k0));                            \
        cp16(&sm->Bs[buf][bk0][bn], &W[(size_t)((k0) + bk0) * N + colBase + bn]); \
        cp16(&sm->Bs[buf][bk1][bn], &W[(size_t)((k0) + bk1) * N + colBase + bn]); \
        asm volatile("cp.async.commit_group;" ::: "memory");                   \
    } while (0)

    // prologue: 3 tiles in flight
    LOAD_TILE(0, 0);
    LOAD_TILE(1, GBK);
    LOAD_TILE(2, 2 * GBK);

    for (int it = 0; it < nIter; it++) {
        const int buf = it & 3;
        if (it + 2 < nIter)
            asm volatile("cp.async.wait_group 2;" ::: "memory");
        else if (it + 1 < nIter)
            asm volatile("cp.async.wait_group 1;" ::: "memory");
        else
            asm volatile("cp.async.wait_group 0;" ::: "memory");
        __syncthreads();   // single barrier per iteration

#pragma unroll
        for (int kk = 0; kk < GBK; kk += 8) {
            // --- batch ALL fragment loads first (24 independent LDS) ---
            uint32_t araw[2][4];
            uint32_t braw[8][2];
#pragma unroll
            for (int mi = 0; mi < 2; mi++) {
                int mrow = warpM * 32 + mi * 16;
                araw[mi][0] = sm->As[buf][mrow + g    ][kk + tig    ];
                araw[mi][1] = sm->As[buf][mrow + g + 8][kk + tig    ];
                araw[mi][2] = sm->As[buf][mrow + g    ][kk + tig + 4];
                araw[mi][3] = sm->As[buf][mrow + g + 8][kk + tig + 4];
            }
#pragma unroll
            for (int ni = 0; ni < 8; ni++) {
                int ncol = warpN * 64 + ni * 8;
                braw[ni][0] = sm->Bs[buf][kk + tig    ][ncol + g];
                braw[ni][1] = sm->Bs[buf][kk + tig + 4][ncol + g];
            }

            // --- batch the CVTs ---
            uint32_t af[2][4];
#pragma unroll
            for (int mi = 0; mi < 2; mi++)
#pragma unroll
                for (int e = 0; e < 4; e++) af[mi][e] = rna(araw[mi][e]);
#pragma unroll
            for (int ni = 0; ni < 8; ni++) {
                braw[ni][0] = rna(braw[ni][0]);
                braw[ni][1] = rna(braw[ni][1]);
            }

            // --- issue the 16 MMAs back-to-back ---
#pragma unroll
            for (int ni = 0; ni < 8; ni++) {
                mma_tf32(acc[0][ni], af[0], braw[ni][0], braw[ni][1]);
                mma_tf32(acc[1][ni], af[1], braw[ni][0], braw[ni][1]);
            }
        }

        // load tile it+3 into buffer (it+3)&3 (held tile it-1; safe past barrier)
        if (it + 3 < nIter)
            LOAD_TILE((it + 3) & 3, (it + 3) * GBK);
    }
#undef LOAD_TILE

    // epilogue
#pragma unroll
    for (int mi = 0; mi < 2; mi++) {
        int r0 = rowBase + warpM * 32 + mi * 16 + g;
        int r1 = r0 + 8;
#pragma unroll
        for (int ni = 0; ni < 8; ni++) {
            int c0 = colBase + warpN * 64 + ni * 8 + tig * 2;
            float bz0 = __ldg(&bias[c0]);
            float bz1 = __ldg(&bias[c0 + 1]);
            float2 v0 = make_float2(acc[mi][ni][0] + bz0, acc[mi][ni][1] + bz1);
            float2 v1 = make_float2(acc[mi][ni][2] + bz0, acc[mi][ni][3] + bz1);
            *(float2*)&C[(size_t)r0 * N + c0] = v0;
            *(float2*)&C[(size_t)r1 * N + c0] = v1;
        }
    }
}

__global__ __launch_bounds__(256) void gemm_tf32_bias(
    const float* __restrict__ A, const float* __restrict__ W,
    const float* __restrict__ bias, float* __restrict__ C,
    int N, int Kdim)
{
    extern __shared__ uint8_t smem_raw[];
    gemm_body(A, W, bias, C, N, Kdim, blockIdx.y * GBM, blockIdx.x * GBN,
              reinterpret_cast<GemmSmem4*>(smem_raw));
}

// fused dual-output GEMM: same A, two weight/bias/output sets
__global__ __launch_bounds__(256) void gemm_tf32_bias_dual(
    const float* __restrict__ A,
    const float* __restrict__ W1, const float* __restrict__ b1, float* __restrict__ C1, int N1,
    const float* __restrict__ W2, const float* __restrict__ b2, float* __restrict__ C2, int N2,
    int Kdim)
{
    extern __shared__ uint8_t smem_raw[];
    GemmSmem4* sm = reinterpret_cast<GemmSmem4*>(smem_raw);
    const int nb1 = N1 / GBN;
    if ((int)blockIdx.x < nb1)
        gemm_body(A, W1, b1, C1, N1, Kdim, blockIdx.y * GBM, blockIdx.x * GBN, sm);
    else
        gemm_body(A, W2, b2, C2, N2, Kdim, blockIdx.y * GBM, (blockIdx.x - nb1) * GBN, sm);
}

// =====================================================================
// Segmented GEMM: q-projection + all 4 key projections in ONE launch.
// y-blocks: [0,128) q | [128,136) k0 | [136,168) k1 | [168,296) k2 | [296,808) k3
// =====================================================================
__global__ __launch_bounds__(256) void gemm_tf32_seg(
    const float* __restrict__ query,
    const float* __restrict__ k0p, const float* __restrict__ k1p,
    const float* __restrict__ k2p, const float* __restrict__ k3p,
    const float* __restrict__ Wq, const float* __restrict__ bq,
    const float* __restrict__ Wk, const float* __restrict__ bk,
    float* __restrict__ qOut, float* __restrict__ kfOut)
{
    extern __shared__ uint8_t smem_raw[];
    GemmSmem4* sm = reinterpret_cast<GemmSmem4*>(smem_raw);
    const int yb = blockIdx.y;

    const float* A;
    const float* W;
    const float* bias;
    float* C;
    int rowBase;

    if (yb < 128)      { A = query; W = Wq; bias = bq; C = qOut;            rowBase = yb * GBM; }
    else if (yb < 136) { A = k0p;   W = Wk; bias = bk; C = kfOut;           rowBase = (yb - 128) * GBM; }
    else if (yb < 168) { A = k1p;   W = Wk; bias = bk; C = kfOut + 262144;  rowBase = (yb - 136) * GBM; }
    else if (yb < 296) { A = k2p;   W = Wk; bias = bk; C = kfOut + 1310720; rowBase = (yb - 168) * GBM; }
    else               { A = k3p;   W = Wk; bias = bk; C = kfOut + 5505024; rowBase = (yb - 296) * GBM; }

    gemm_body(A, W, bias, C, DMODEL, DMODEL, rowBase, blockIdx.x * GBN, sm);
}

// ---------------- bilinear sample + softmax + aggregation ----------------
// One warp per (b, head, pixel); lane = channel d (0..31).
__global__ void sample_agg_kernel(const float* __restrict__ ref_point)
{
    int gtid = blockIdx.x * blockDim.x + threadIdx.x;
    int warp = gtid >> 5;
    int lane = gtid & 31;
    if (warp >= NB * NHEADS * HWQ) return;

    int pix = warp & (HWQ - 1);
    int bh  = warp >> 12;            // b*8 + h
    int b   = bh >> 3;
    int h   = bh & 7;

    float rx = ref_point[pix * 2 + 0];
    float ry = ref_point[pix * 2 + 1];

    const float* offrow = g_off + (size_t)(b * HWQ + pix) * DMODEL + h * 32;
    const float* lrow   = g_A   + (size_t)(b * HWQ + pix) * 128    + h * 16;

    // coalesced: lane j loads offset element j (32 floats) and logit j (<16)
    float off_reg = __ldg(&offrow[lane]);
    float lv = (lane < 16) ? __ldg(&lrow[lane]) : -1e30f;

    // warp softmax over 16 logits via butterfly
    float mx = lv;
#pragma unroll
    for (int d = 16; d; d >>= 1) mx = fmaxf(mx, __shfl_xor_sync(0xFFFFFFFFu, mx, d));
    float e = __expf(lv - mx);
    float ssum = e;
#pragma unroll
    for (int d = 16; d; d >>= 1) ssum += __shfl_xor_sync(0xFFFFFFFFu, ssum, d);
    float wnorm = e / ssum;          // valid on lanes 0..15

    float acc = 0.f;

    const int wls[4]   = {16, 32, 64, 128};
    const int bases[4] = {0, 262144, 1310720, 5505024};

#pragma unroll
    for (int s = 0; s < 4; s++) {
        const int wl = wls[s];
        const float* kfb = g_kf + bases[s] + (size_t)b * wl * wl * DMODEL + h * 32 + lane;
        const float fwl  = (float)wl;
        const float fwm1 = (float)(wl - 1);
        const float rxs = rx * fwm1;
        const float rys = ry * fwm1;

#pragma unroll
        for (int k = 0; k < 4; k++) {
            float ox = __shfl_sync(0xFFFFFFFFu, off_reg, s * 8 + k * 2);
            float oy = __shfl_sync(0xFFFFFFFFu, off_reg, s * 8 + k * 2 + 1);
            float wgt = __shfl_sync(0xFFFFFFFFu, wnorm, s * 4 + k);

            float px = rxs + ox;
            float py = rys + oy;
            float gx = 2.f * px / fwm1 - 1.f;
            float gy = 2.f * py / fwm1 - 1.f;
            float ix = ((gx + 1.f) * fwl - 1.f) * 0.5f;
            float iy = ((gy + 1.f) * fwl - 1.f) * 0.5f;

            float x0f = floorf(ix), y0f = floorf(iy);
            int x0 = (int)x0f, y0 = (int)y0f;
            float wx1 = ix - x0f, wy1 = iy - y0f;
            float wx0 = 1.f - wx1, wy0 = 1.f - wy1;

            bool inx0 = (x0 >= 0) & (x0 < wl);
            bool inx1 = (x0 + 1 >= 0) & (x0 + 1 < wl);
            bool iny0 = (y0 >= 0) & (y0 < wl);
            bool iny1 = (y0 + 1 >= 0) & (y0 + 1 < wl);

            float v = 0.f;
            if (inx0 & iny0) v += wx0 * wy0 * __ldg(&kfb[((size_t)y0 * wl + x0)       * DMODEL]);
            if (inx1 & iny0) v += wx1 * wy0 * __ldg(&kfb[((size_t)y0 * wl + x0 + 1)   * DMODEL]);
            if (inx0 & iny1) v += wx0 * wy1 * __ldg(&kfb[((size_t)(y0+1) * wl + x0)   * DMODEL]);
            if (inx1 & iny1) v += wx1 * wy1 * __ldg(&kfb[((size_t)(y0+1) * wl + x0+1) * DMODEL]);

            acc += wgt * v;
        }
    }

    g_F[(size_t)warp * 32 + lane] = acc;
}

// ---------------- launch ----------------
extern "C" void kernel_launch(void* const* d_in, const int* in_sizes, int n_in,
                              void* d_out, int out_size)
{
    const float *query, *ref_point, *Wq, *bq, *Wk, *bk, *Woff, *boff, *WA, *bA, *Wm, *bm;
    const float* keys[4];

    if (in_sizes[1] == 262144) {
        // reference-signature order
        query     = (const float*)d_in[0];
        keys[0]   = (const float*)d_in[1];
        keys[1]   = (const float*)d_in[2];
        keys[2]   = (const float*)d_in[3];
        keys[3]   = (const float*)d_in[4];
        ref_point = (const float*)d_in[5];
        Wq   = (const float*)d_in[6];
        bq   = (const float*)d_in[7];
        Wk   = (const float*)d_in[8];
        bk   = (const float*)d_in[9];
        Woff = (const float*)d_in[10];
        boff = (const float*)d_in[11];
        WA   = (const float*)d_in[12];
        bA   = (const float*)d_in[13];
        Wm   = (const float*)d_in[14];
        bm   = (const float*)d_in[15];
    } else {
        // setup_inputs dict order
        query     = (const float*)d_in[0];
        ref_point = (const float*)d_in[1];
        Wq   = (const float*)d_in[2];
        bq   = (const float*)d_in[3];
        Wk   = (const float*)d_in[4];
        bk   = (const float*)d_in[5];
        Woff = (const float*)d_in[6];
        boff = (const float*)d_in[7];
        WA   = (const float*)d_in[8];
        bA   = (const float*)d_in[9];
        Wm   = (const float*)d_in[10];
        bm   = (const float*)d_in[11];
        keys[0] = (const float*)d_in[12];
        keys[1] = (const float*)d_in[13];
        keys[2] = (const float*)d_in[14];
        keys[3] = (const float*)d_in[15];
    }
    float* out = (float*)d_out;

    float *q, *off, *A, *kf, *F;
    cudaGetSymbolAddress((void**)&q,   g_q);
    cudaGetSymbolAddress((void**)&off, g_off);
    cudaGetSymbolAddress((void**)&A,   g_A);
    cudaGetSymbolAddress((void**)&kf,  g_kf);
    cudaGetSymbolAddress((void**)&F,   g_F);

    // opt-in to >48KB dynamic smem (executes immediately; not captured)
    cudaFuncSetAttribute(gemm_tf32_seg,
                         cudaFuncAttributeMaxDynamicSharedMemorySize, (int)GEMM_SMEM_BYTES);
    cudaFuncSetAttribute(gemm_tf32_bias_dual,
                         cudaFuncAttributeMaxDynamicSharedMemorySize, (int)GEMM_SMEM_BYTES);
    cudaFuncSetAttribute(gemm_tf32_bias,
                         cudaFuncAttributeMaxDynamicSharedMemorySize, (int)GEMM_SMEM_BYTES);

    // 1. segmented GEMM: q-proj + all key projections (one launch, 1616 blocks)
    gemm_tf32_seg<<<dim3(2, 808), 256, GEMM_SMEM_BYTES>>>(
        query, keys[0], keys[1], keys[2], keys[3], Wq, bq, Wk, bk, q, kf);

    // 2. dual: off = q@Woff+boff (N=256), A-logits = q@WA+bA (N=128)
    gemm_tf32_bias_dual<<<dim3(DMODEL / GBN + 128 / GBN, MQ / GBM), 256, GEMM_SMEM_BYTES>>>(
        q, Woff, boff, off, DMODEL, WA, bA, A, 128, DMODEL);

    // 3. bilinear sampling + softmax + aggregation -> F
    {
        int nthreads = NB * NHEADS * HWQ * 32;
        sample_agg_kernel<<<nthreads / 256, 256>>>(ref_point);
    }

    // 4. out = F @ Wm + bm
    gemm_tf32_bias<<<dim3(DMODEL / GBN, MQ / GBM), 256, GEMM_SMEM_BYTES>>>(F, Wm, bm, out, DMODEL, DMODEL);
}

// round 13
// speedup vs baseline: 2.2694x; 1.0523x over previous
#include <cuda_runtime.h>
#include <math.h>
#include <stdint.h>

// ---------------- problem constants ----------------
#define NHEADS   8
#define NK       4
#define NSCALES  4
#define DMODEL   256
#define DKH      32
#define NB       4
#define QH       64
#define QW       64
#define HWQ      (QH*QW)      // 4096
#define MQ       (NB*HWQ)     // 16384

#define KF_TOTAL 22282240

// prepped-weight offsets (floats)
#define WQP_OFF   0
#define WKP_OFF   65536
#define WOFFP_OFF 131072
#define WAP_OFF   196608
#define WMP_OFF   229376
#define WP_TOTAL  294912

// ---------------- scratch ----------------
__device__ float g_q  [MQ * DMODEL];    // q projection, stored RNA-rounded to tf32
__device__ float g_off[MQ * DMODEL];    // offsets, fp32
__device__ float g_A  [MQ * 128];       // raw attention logits, fp32
__device__ float g_kf [KF_TOTAL];       // projected keys, fp32
__device__ float g_F  [MQ * DMODEL];    // aggregated features, RNA-rounded to tf32
__device__ float g_Wp [WP_TOTAL];       // pre-rounded, permuted weights

// =====================================================================
// TF32 tensor-core GEMM, 4-stage cp.async pipeline, ONE barrier/iter.
// B operand comes from pre-rounded permuted weights -> LDS.64, no CVT.
// =====================================================================
#define GBM 128
#define GBN 128
#define GBK 16
#define NSTAGE 4
#define ASTR 20    // As row stride in words, [m][k] layout -> conflict-free frags

struct GemmSmem4 {
    uint32_t As[NSTAGE][GBM][ASTR];   // 4 * 10240 B
    uint32_t Bt[NSTAGE][GBN][16];     // 4 *  8192 B  (permuted weight tiles)
};
#define GEMM_SMEM_BYTES (sizeof(GemmSmem4))   // 73728

__device__ __forceinline__ void cp16(void* smem, const void* gmem) {
    uint32_t s = (uint32_t)__cvta_generic_to_shared(smem);
    asm volatile("cp.async.ca.shared.global [%0], [%1], 16;" :: "r"(s), "l"(gmem));
}

__device__ __forceinline__ uint32_t rna(uint32_t fbits) {
    uint32_t u;
    asm("cvt.rna.tf32.f32 %0, %1;" : "=r"(u) : "r"(fbits));
    return u;
}

__device__ __forceinline__ float rnaf(float f) {
    return __uint_as_float(rna(__float_as_uint(f)));
}

__device__ __forceinline__ void mma_tf32(float* c, const uint32_t* a, uint32_t b0, uint32_t b1) {
    asm volatile(
        "mma.sync.aligned.m16n8k8.row.col.f32.tf32.tf32.f32 "
        "{%0,%1,%2,%3}, {%4,%5,%6,%7}, {%8,%9}, {%0,%1,%2,%3};"
        : "+f"(c[0]), "+f"(c[1]), "+f"(c[2]), "+f"(c[3])
        : "r"(a[0]), "r"(a[1]), "r"(a[2]), "r"(a[3]), "r"(b0), "r"(b1));
}

// ---------------- weight prep: rounded + permuted ----------------
// Wp[weight][kt][n][p] = rna(W[kt*16 + (p>>2) + 4*(p&3)][n])
__global__ void prep_weights(
    const float* __restrict__ Wq, const float* __restrict__ Wk,
    const float* __restrict__ Woff, const float* __restrict__ WA,
    const float* __restrict__ Wm)
{
    int i = blockIdx.x * blockDim.x + threadIdx.x;
    if (i >= WP_TOTAL) return;
    const float* W; int N; int base;
    if (i < WKP_OFF)        { W = Wq;   N = 256; base = WQP_OFF; }
    else if (i < WOFFP_OFF) { W = Wk;   N = 256; base = WKP_OFF; }
    else if (i < WAP_OFF)   { W = Woff; N = 256; base = WOFFP_OFF; }
    else if (i < WMP_OFF)   { W = WA;   N = 128; base = WAP_OFF; }
    else                    { W = Wm;   N = 256; base = WMP_OFF; }
    int loc = i - base;
    int kt  = loc / (16 * N);
    int rem = loc - kt * 16 * N;
    int n   = rem >> 4;
    int p   = rem & 15;
    int k   = kt * 16 + (p >> 2) + 4 * (p & 3);
    g_Wp[i] = rnaf(__ldg(&W[(size_t)k * N + n]));
}

// ---------------- GEMM body ----------------
// Wp: prepped weight base.  CVT_A: round A fragments (raw fp32 inputs).
// round_out: RNA-round outputs (for activations consumed as later A operands).
template<bool CVT_A>
__device__ __forceinline__ void gemm_body(
    const float* __restrict__ A,
    const float* __restrict__ Wp,
    const float* __restrict__ bias,
    float* __restrict__ C,
    int N, int Kdim, int rowBase, int colBase, bool round_out,
    GemmSmem4* sm)
{
    const int tid  = threadIdx.x;
    const int lane = tid & 31;
    const int warp = tid >> 5;
    const int warpM = warp & 3;
    const int warpN = warp >> 2;
    const int g    = lane >> 2;
    const int tig  = lane & 3;

    const int am0 = tid >> 2;
    const int am1 = am0 + 64;
    const int ak4 = (tid & 3) * 4;
    // B loader: 128 rows x 4 chunks = 512 chunks, 2 per thread
    const int br0 = tid >> 2;            // row 0..63
    const int bc  = (tid & 3) * 4;       // chunk word offset

    const float* Arow0 = &A[(size_t)(rowBase + am0) * Kdim + ak4];
    const float* Arow1 = &A[(size_t)(rowBase + am1) * Kdim + ak4];

    float acc[2][8][4];
#pragma unroll
    for (int mi = 0; mi < 2; mi++)
#pragma unroll
        for (int ni = 0; ni < 8; ni++)
#pragma unroll
            for (int e = 0; e < 4; e++) acc[mi][ni][e] = 0.f;

    const int nIter = Kdim / GBK;   // 16 for all our calls

#define LOAD_TILE(buf, k0)                                                        \
    do {                                                                          \
        cp16(&sm->As[buf][am0][ak4], Arow0 + (k0));                               \
        cp16(&sm->As[buf][am1][ak4], Arow1 + (k0));                               \
        const float* slab = Wp + (size_t)(k0) * N + (size_t)colBase * 16;         \
        cp16(&sm->Bt[buf][br0     ][bc], slab + (size_t)(br0     ) * 16 + bc);    \
        cp16(&sm->Bt[buf][br0 + 64][bc], slab + (size_t)(br0 + 64) * 16 + bc);    \
        asm volatile("cp.async.commit_group;" ::: "memory");                      \
    } while (0)

    // prologue: 3 tiles in flight
    LOAD_TILE(0, 0);
    LOAD_TILE(1, GBK);
    LOAD_TILE(2, 2 * GBK);

    for (int it = 0; it < nIter; it++) {
        const int buf = it & 3;
        if (it + 2 < nIter)
            asm volatile("cp.async.wait_group 2;" ::: "memory");
        else if (it + 1 < nIter)
            asm volatile("cp.async.wait_group 1;" ::: "memory");
        else
            asm volatile("cp.async.wait_group 0;" ::: "memory");
        __syncthreads();   // single barrier per iteration

#pragma unroll
        for (int kk = 0; kk < GBK; kk += 8) {
            uint32_t af[2][4];
#pragma unroll
            for (int mi = 0; mi < 2; mi++) {
                int mrow = warpM * 32 + mi * 16;
                uint32_t a0 = sm->As[buf][mrow + g    ][kk + tig    ];
                uint32_t a1 = sm->As[buf][mrow + g + 8][kk + tig    ];
                uint32_t a2 = sm->As[buf][mrow + g    ][kk + tig + 4];
                uint32_t a3 = sm->As[buf][mrow + g + 8][kk + tig + 4];
                if (CVT_A) { a0 = rna(a0); a1 = rna(a1); a2 = rna(a2); a3 = rna(a3); }
                af[mi][0] = a0; af[mi][1] = a1; af[mi][2] = a2; af[mi][3] = a3;
            }
            const int boff = 4 * tig + ((kk >> 2) & 2);   // kk=0 -> +0, kk=8 -> +2
#pragma unroll
            for (int ni = 0; ni < 8; ni++) {
                int ncol = warpN * 64 + ni * 8;
                uint2 bv = *(const uint2*)&sm->Bt[buf][ncol + g][boff];
                mma_tf32(acc[0][ni], af[0], bv.x, bv.y);
                mma_tf32(acc[1][ni], af[1], bv.x, bv.y);
            }
        }

        if (it + 3 < nIter)
            LOAD_TILE((it + 3) & 3, (it + 3) * GBK);
    }
#undef LOAD_TILE

    // epilogue
#pragma unroll
    for (int mi = 0; mi < 2; mi++) {
        int r0 = rowBase + warpM * 32 + mi * 16 + g;
        int r1 = r0 + 8;
#pragma unroll
        for (int ni = 0; ni < 8; ni++) {
            int c0 = colBase + warpN * 64 + ni * 8 + tig * 2;
            float bz0 = __ldg(&bias[c0]);
            float bz1 = __ldg(&bias[c0 + 1]);
            float o00 = acc[mi][ni][0] + bz0, o01 = acc[mi][ni][1] + bz1;
            float o10 = acc[mi][ni][2] + bz0, o11 = acc[mi][ni][3] + bz1;
            if (round_out) { o00 = rnaf(o00); o01 = rnaf(o01); o10 = rnaf(o10); o11 = rnaf(o11); }
            *(float2*)&C[(size_t)r0 * N + c0] = make_float2(o00, o01);
            *(float2*)&C[(size_t)r1 * N + c0] = make_float2(o10, o11);
        }
    }
}

__global__ __launch_bounds__(256) void gemm_tf32_bias(
    const float* __restrict__ A, const float* __restrict__ Wp,
    const float* __restrict__ bias, float* __restrict__ C,
    int N, int Kdim)
{
    extern __shared__ uint8_t smem_raw[];
    gemm_body<false>(A, Wp, bias, C, N, Kdim, blockIdx.y * GBM, blockIdx.x * GBN,
                     false, reinterpret_cast<GemmSmem4*>(smem_raw));
}

// fused dual-output GEMM: same A (pre-rounded), two prepped weights
__global__ __launch_bounds__(256) void gemm_tf32_bias_dual(
    const float* __restrict__ A,
    const float* __restrict__ Wp1, const float* __restrict__ b1, float* __restrict__ C1, int N1,
    const float* __restrict__ Wp2, const float* __restrict__ b2, float* __restrict__ C2, int N2,
    int Kdim)
{
    extern __shared__ uint8_t smem_raw[];
    GemmSmem4* sm = reinterpret_cast<GemmSmem4*>(smem_raw);
    const int nb1 = N1 / GBN;
    if ((int)blockIdx.x < nb1)
        gemm_body<false>(A, Wp1, b1, C1, N1, Kdim, blockIdx.y * GBM, blockIdx.x * GBN, false, sm);
    else
        gemm_body<false>(A, Wp2, b2, C2, N2, Kdim, blockIdx.y * GBM, (blockIdx.x - nb1) * GBN, false, sm);
}

// =====================================================================
// Segmented GEMM: q-projection + all 4 key projections in ONE launch.
// A = raw fp32 inputs -> CVT_A=true. q output rounded; kf outputs fp32.
// y-blocks: [0,128) q | [128,136) k0 | [136,168) k1 | [168,296) k2 | [296,808) k3
// =====================================================================
__global__ __launch_bounds__(256) void gemm_tf32_seg(
    const float* __restrict__ query,
    const float* __restrict__ k0p, const float* __restrict__ k1p,
    const float* __restrict__ k2p, const float* __restrict__ k3p,
    const float* __restrict__ bq, const float* __restrict__ bk,
    float* __restrict__ qOut, float* __restrict__ kfOut)
{
    extern __shared__ uint8_t smem_raw[];
    GemmSmem4* sm = reinterpret_cast<GemmSmem4*>(smem_raw);
    const int yb = blockIdx.y;

    const float* A;
    const float* Wp;
    const float* bias;
    float* C;
    int rowBase;
    bool round_out = false;

    if (yb < 128)      { A = query; Wp = g_Wp + WQP_OFF; bias = bq; C = qOut;            rowBase = yb * GBM; round_out = true; }
    else if (yb < 136) { A = k0p;   Wp = g_Wp + WKP_OFF; bias = bk; C = kfOut;           rowBase = (yb - 128) * GBM; }
    else if (yb < 168) { A = k1p;   Wp = g_Wp + WKP_OFF; bias = bk; C = kfOut + 262144;  rowBase = (yb - 136) * GBM; }
    else if (yb < 296) { A = k2p;   Wp = g_Wp + WKP_OFF; bias = bk; C = kfOut + 1310720; rowBase = (yb - 168) * GBM; }
    else               { A = k3p;   Wp = g_Wp + WKP_OFF; bias = bk; C = kfOut + 5505024; rowBase = (yb - 296) * GBM; }

    gemm_body<true>(A, Wp, bias, C, DMODEL, DMODEL, rowBase, blockIdx.x * GBN, round_out, sm);
}

// ---------------- bilinear sample + softmax + aggregation ----------------
// One warp per (b, head, pixel); lane = channel d (0..31).
__global__ void sample_agg_kernel(const float* __restrict__ ref_point)
{
    int gtid = blockIdx.x * blockDim.x + threadIdx.x;
    int warp = gtid >> 5;
    int lane = gtid & 31;
    if (warp >= NB * NHEADS * HWQ) return;

    int pix = warp & (HWQ - 1);
    int bh  = warp >> 12;            // b*8 + h
    int b   = bh >> 3;
    int h   = bh & 7;

    float rx = ref_point[pix * 2 + 0];
    float ry = ref_point[pix * 2 + 1];

    const float* offrow = g_off + (size_t)(b * HWQ + pix) * DMODEL + h * 32;
    const float* lrow   = g_A   + (size_t)(b * HWQ + pix) * 128    + h * 16;

    float off_reg = __ldg(&offrow[lane]);
    float lv = (lane < 16) ? __ldg(&lrow[lane]) : -1e30f;

    // warp softmax over 16 logits via butterfly
    float mx = lv;
#pragma unroll
    for (int d = 16; d; d >>= 1) mx = fmaxf(mx, __shfl_xor_sync(0xFFFFFFFFu, mx, d));
    float e = __expf(lv - mx);
    float ssum = e;
#pragma unroll
    for (int d = 16; d; d >>= 1) ssum += __shfl_xor_sync(0xFFFFFFFFu, ssum, d);
    float wnorm = e / ssum;          // valid on lanes 0..15

    float acc = 0.f;

    const int wls[4]   = {16, 32, 64, 128};
    const int bases[4] = {0, 262144, 1310720, 5505024};

#pragma unroll
    for (int s = 0; s < 4; s++) {
        const int wl = wls[s];
        const float* kfb = g_kf + bases[s] + (size_t)b * wl * wl * DMODEL + h * 32 + lane;
        const float fwl  = (float)wl;
        const float fwm1 = (float)(wl - 1);
        const float rxs = rx * fwm1;
        const float rys = ry * fwm1;

#pragma unroll
        for (int k = 0; k < 4; k++) {
            float ox = __shfl_sync(0xFFFFFFFFu, off_reg, s * 8 + k * 2);
            float oy = __shfl_sync(0xFFFFFFFFu, off_reg, s * 8 + k * 2 + 1);
            float wgt = __shfl_sync(0xFFFFFFFFu, wnorm, s * 4 + k);

            float px = rxs + ox;
            float py = rys + oy;
            float gx = 2.f * px / fwm1 - 1.f;
            float gy = 2.f * py / fwm1 - 1.f;
            float ix = ((gx + 1.f) * fwl - 1.f) * 0.5f;
            float iy = ((gy + 1.f) * fwl - 1.f) * 0.5f;

            float x0f = floorf(ix), y0f = floorf(iy);
            int x0 = (int)x0f, y0 = (int)y0f;
            float wx1 = ix - x0f, wy1 = iy - y0f;
            float wx0 = 1.f - wx1, wy0 = 1.f - wy1;

            bool inx0 = (x0 >= 0) & (x0 < wl);
            bool inx1 = (x0 + 1 >= 0) & (x0 + 1 < wl);
            bool iny0 = (y0 >= 0) & (y0 < wl);
            bool iny1 = (y0 + 1 >= 0) & (y0 + 1 < wl);

            float v = 0.f;
            if (inx0 & iny0) v += wx0 * wy0 * __ldg(&kfb[((size_t)y0 * wl + x0)       * DMODEL]);
            if (inx1 & iny0) v += wx1 * wy0 * __ldg(&kfb[((size_t)y0 * wl + x0 + 1)   * DMODEL]);
            if (inx0 & iny1) v += wx0 * wy1 * __ldg(&kfb[((size_t)(y0+1) * wl + x0)   * DMODEL]);
            if (inx1 & iny1) v += wx1 * wy1 * __ldg(&kfb[((size_t)(y0+1) * wl + x0+1) * DMODEL]);

            acc += wgt * v;
        }
    }

    // F is consumed only as a GEMM A-operand: store pre-rounded (same value
    // the out-GEMM previously computed at fragment load).
    g_F[(size_t)warp * 32 + lane] = rnaf(acc);
}

// ---------------- launch ----------------
extern "C" void kernel_launch(void* const* d_in, const int* in_sizes, int n_in,
                              void* d_out, int out_size)
{
    const float *query, *ref_point, *Wq, *bq, *Wk, *bk, *Woff, *boff, *WA, *bA, *Wm, *bm;
    const float* keys[4];

    if (in_sizes[1] == 262144) {
        // reference-signature order
        query     = (const float*)d_in[0];
        keys[0]   = (const float*)d_in[1];
        keys[1]   = (const float*)d_in[2];
        keys[2]   = (const float*)d_in[3];
        keys[3]   = (const float*)d_in[4];
        ref_point = (const float*)d_in[5];
        Wq   = (const float*)d_in[6];
        bq   = (const float*)d_in[7];
        Wk   = (const float*)d_in[8];
        bk   = (const float*)d_in[9];
        Woff = (const float*)d_in[10];
        boff = (const float*)d_in[11];
        WA   = (const float*)d_in[12];
        bA   = (const float*)d_in[13];
        Wm   = (const float*)d_in[14];
        bm   = (const float*)d_in[15];
    } else {
        // setup_inputs dict order
        query     = (const float*)d_in[0];
        ref_point = (const float*)d_in[1];
        Wq   = (const float*)d_in[2];
        bq   = (const float*)d_in[3];
        Wk   = (const float*)d_in[4];
        bk   = (const float*)d_in[5];
        Woff = (const float*)d_in[6];
        boff = (const float*)d_in[7];
        WA   = (const float*)d_in[8];
        bA   = (const float*)d_in[9];
        Wm   = (const float*)d_in[10];
        bm   = (const float*)d_in[11];
        keys[0] = (const float*)d_in[12];
        keys[1] = (const float*)d_in[13];
        keys[2] = (const float*)d_in[14];
        keys[3] = (const float*)d_in[15];
    }
    float* out = (float*)d_out;

    float *q, *off, *A, *kf, *F, *Wp;
    cudaGetSymbolAddress((void**)&q,   g_q);
    cudaGetSymbolAddress((void**)&off, g_off);
    cudaGetSymbolAddress((void**)&A,   g_A);
    cudaGetSymbolAddress((void**)&kf,  g_kf);
    cudaGetSymbolAddress((void**)&F,   g_F);
    cudaGetSymbolAddress((void**)&Wp,  g_Wp);

    cudaFuncSetAttribute(gemm_tf32_seg,
                         cudaFuncAttributeMaxDynamicSharedMemorySize, (int)GEMM_SMEM_BYTES);
    cudaFuncSetAttribute(gemm_tf32_bias_dual,
                         cudaFuncAttributeMaxDynamicSharedMemorySize, (int)GEMM_SMEM_BYTES);
    cudaFuncSetAttribute(gemm_tf32_bias,
                         cudaFuncAttributeMaxDynamicSharedMemorySize, (int)GEMM_SMEM_BYTES);

    // 0. prep weights: round + permute (tiny)
    prep_weights<<<WP_TOTAL / 256, 256>>>(Wq, Wk, Woff, WA, Wm);

    // 1. segmented GEMM: q-proj + all key projections (one launch, 1616 blocks)
    gemm_tf32_seg<<<dim3(2, 808), 256, GEMM_SMEM_BYTES>>>(
        query, keys[0], keys[1], keys[2], keys[3], bq, bk, q, kf);

    // 2. dual: off = q@Woff+boff (N=256), A-logits = q@WA+bA (N=128)
    gemm_tf32_bias_dual<<<dim3(DMODEL / GBN + 128 / GBN, MQ / GBM), 256, GEMM_SMEM_BYTES>>>(
        q, Wp + WOFFP_OFF, boff, off, DMODEL, Wp + WAP_OFF, bA, A, 128, DMODEL);

    // 3. bilinear sampling + softmax + aggregation -> F (rounded)
    {
        int nthreads = NB * NHEADS * HWQ * 32;
        sample_agg_kernel<<<nthreads / 256, 256>>>(ref_point);
    }

    // 4. out = F @ Wm + bm
    gemm_tf32_bias<<<dim3(DMODEL / GBN, MQ / GBM), 256, GEMM_SMEM_BYTES>>>(
        F, Wp + WMP_OFF, bm, out, DMODEL, DMODEL);
}